// round 1
// baseline (speedup 1.0000x reference)
#include <cuda_runtime.h>
#include <math.h>

#define BZ 2
#define TZ 2048
#define CZ 1024
#define HH 16
#define DD 64
#define M_TOT (BZ * TZ)      // 4096
#define N_QKV (3 * CZ)       // 3072
#define K_DIM CZ             // 1024

// Scratch (allocation-free rule: __device__ globals)
__device__ float g_q[BZ * HH * TZ * DD];
__device__ float g_k[BZ * HH * TZ * DD];
__device__ float g_v[BZ * HH * TZ * DD];
__device__ float g_y[BZ * TZ * CZ];

// ---------------------------------------------------------------------------
// SGEMM: C[M,N] = A[M,K] * B[K,N] + bias[N]
// 128x128 tile, BK=8, 256 threads, 8x8 per thread.
// QKV=true: scatter epilogue into g_q/g_k/g_v in [B,H,T,D] layout.
// QKV=false: plain row-major store to Cout.
// All dims are multiples of tile sizes -> no bounds checks.
// ---------------------------------------------------------------------------
template <bool QKV>
__global__ __launch_bounds__(256) void gemm_kernel(
    const float* __restrict__ A, const float* __restrict__ Bm,
    const float* __restrict__ bias, float* __restrict__ Cout, int N)
{
    __shared__ float As[8][128];
    __shared__ float Bs[8][128];

    const int tid = threadIdx.x;
    const int bm = blockIdx.y * 128;
    const int bn = blockIdx.x * 128;

    const int arow = tid >> 1;          // 0..127
    const int acol = (tid & 1) * 4;     // 0 or 4
    const int brow = tid >> 5;          // 0..7
    const int bcol = (tid & 31) * 4;    // 0..124

    const int tx = (tid & 15) * 8;
    const int ty = (tid >> 4) * 8;

    float acc[8][8];
#pragma unroll
    for (int i = 0; i < 8; i++)
#pragma unroll
        for (int j = 0; j < 8; j++) acc[i][j] = 0.f;

    for (int kt = 0; kt < K_DIM; kt += 8) {
        float4 av = *(const float4*)&A[(size_t)(bm + arow) * K_DIM + kt + acol];
        As[acol + 0][arow] = av.x;
        As[acol + 1][arow] = av.y;
        As[acol + 2][arow] = av.z;
        As[acol + 3][arow] = av.w;
        float4 bv = *(const float4*)&Bm[(size_t)(kt + brow) * N + bn + bcol];
        *(float4*)&Bs[brow][bcol] = bv;
        __syncthreads();

#pragma unroll
        for (int k = 0; k < 8; k++) {
            float ra[8], rb[8];
#pragma unroll
            for (int i = 0; i < 8; i++) ra[i] = As[k][ty + i];
#pragma unroll
            for (int j = 0; j < 8; j++) rb[j] = Bs[k][tx + j];
#pragma unroll
            for (int i = 0; i < 8; i++)
#pragma unroll
                for (int j = 0; j < 8; j++) acc[i][j] += ra[i] * rb[j];
        }
        __syncthreads();
    }

#pragma unroll
    for (int i = 0; i < 8; i++) {
        const int m = bm + ty + i;
        const int b = m / TZ, t = m % TZ;
#pragma unroll
        for (int j = 0; j < 8; j++) {
            const int n = bn + tx + j;
            const float val = acc[i][j] + bias[n];
            if (QKV) {
                const int sel = n / CZ;      // 0=q 1=k 2=v
                const int cc = n % CZ;
                const int h = cc / DD, d = cc % DD;
                float* dst = (sel == 0) ? g_q : (sel == 1) ? g_k : g_v;
                dst[(((size_t)(b * HH + h)) * TZ + t) * DD + d] = val;
            } else {
                Cout[(size_t)m * N + n] = val;
            }
        }
    }
}

// ---------------------------------------------------------------------------
// Causal flash attention, fp32 scalar. One thread = one query row.
// BQ=64 queries per block, 64 threads. K/V streamed through shared in
// 64x64 tiles. Online softmax with branch-on-new-max (rescale is rare).
// ---------------------------------------------------------------------------
#define BQ 64
#define BKT 64

__global__ __launch_bounds__(64) void attn_kernel()
{
    __shared__ float Ks[BKT][DD];
    __shared__ float Vs[BKT][DD];

    const int tid = threadIdx.x;
    const int q0 = blockIdx.x * BQ;
    const int h  = blockIdx.y;
    const int b  = blockIdx.z;

    const size_t base = ((size_t)(b * HH + h)) * TZ * DD;
    const float* qb = g_q + base;
    const float* kb = g_k + base;
    const float* vb = g_v + base;

    const int q = q0 + tid;

    float qr[DD];
#pragma unroll
    for (int d = 0; d < DD; d++) qr[d] = qb[(size_t)q * DD + d] * 0.125f; // 1/sqrt(64)

    float acc[DD];
#pragma unroll
    for (int d = 0; d < DD; d++) acc[d] = 0.f;
    float mmax = -INFINITY, lsum = 0.f;

    const int nkt = q0 / BKT + 1;  // causal: tiles up to and including diagonal
    for (int kt = 0; kt < nkt; kt++) {
        __syncthreads();  // previous tile fully consumed
        // cooperative load: 64x64 floats = 1024 float4, 16 per thread
#pragma unroll
        for (int i = 0; i < 16; i++) {
            const int idx = i * 64 + tid;
            const int row = idx >> 4;
            const int col = (idx & 15) * 4;
            *(float4*)&Ks[row][col] =
                *(const float4*)&kb[((size_t)(kt * BKT + row)) * DD + col];
            *(float4*)&Vs[row][col] =
                *(const float4*)&vb[((size_t)(kt * BKT + row)) * DD + col];
        }
        __syncthreads();

        const int jmax = (kt == nkt - 1) ? tid : (BKT - 1);
        for (int j = 0; j <= jmax; j++) {
            float s = 0.f;
#pragma unroll
            for (int d4 = 0; d4 < DD; d4 += 4) {
                float4 kv = *(const float4*)&Ks[j][d4];
                s += qr[d4] * kv.x + qr[d4 + 1] * kv.y +
                     qr[d4 + 2] * kv.z + qr[d4 + 3] * kv.w;
            }
            if (s > mmax) {
                const float corr = __expf(mmax - s);
                lsum = lsum * corr + 1.0f;
#pragma unroll
                for (int d4 = 0; d4 < DD; d4 += 4) {
                    float4 vv = *(const float4*)&Vs[j][d4];
                    acc[d4]     = acc[d4]     * corr + vv.x;
                    acc[d4 + 1] = acc[d4 + 1] * corr + vv.y;
                    acc[d4 + 2] = acc[d4 + 2] * corr + vv.z;
                    acc[d4 + 3] = acc[d4 + 3] * corr + vv.w;
                }
                mmax = s;
            } else {
                const float p = __expf(s - mmax);
                lsum += p;
#pragma unroll
                for (int d4 = 0; d4 < DD; d4 += 4) {
                    float4 vv = *(const float4*)&Vs[j][d4];
                    acc[d4]     += p * vv.x;
                    acc[d4 + 1] += p * vv.y;
                    acc[d4 + 2] += p * vv.z;
                    acc[d4 + 3] += p * vv.w;
                }
            }
        }
    }

    const float inv = 1.0f / lsum;
#pragma unroll
    for (int d = 0; d < DD; d++)
        g_y[((size_t)(b * TZ + q)) * CZ + h * DD + d] = acc[d] * inv;
}

// ---------------------------------------------------------------------------
extern "C" void kernel_launch(void* const* d_in, const int* in_sizes, int n_in,
                              void* d_out, int out_size)
{
    const float* x      = (const float*)d_in[0];
    const float* w_attn = (const float*)d_in[1];
    const float* b_attn = (const float*)d_in[2];
    const float* w_proj = (const float*)d_in[3];
    const float* b_proj = (const float*)d_in[4];
    float* out = (float*)d_out;

    void* y_ptr = nullptr;
    cudaGetSymbolAddress(&y_ptr, g_y);

    // 1) QKV GEMM: [4096,1024] x [1024,3072] -> scatter to q/k/v [B,H,T,D]
    {
        dim3 grid(N_QKV / 128, M_TOT / 128);
        gemm_kernel<true><<<grid, 256>>>(x, w_attn, b_attn, nullptr, N_QKV);
    }
    // 2) Causal attention -> g_y [B,T,C]
    {
        dim3 grid(TZ / BQ, HH, BZ);
        attn_kernel<<<grid, 64>>>();
    }
    // 3) Proj GEMM: [4096,1024] x [1024,1024] -> d_out
    {
        dim3 grid(CZ / 128, M_TOT / 128);
        gemm_kernel<false><<<grid, 256>>>((const float*)y_ptr, w_proj, b_proj,
                                          out, CZ);
    }
}

// round 3
// speedup vs baseline: 1.6997x; 1.6997x over previous
#include <cuda_runtime.h>
#include <cstdint>
#include <math.h>

#define BZ 2
#define TZ 2048
#define CZ 1024
#define HH 16
#define DD 64
#define M_TOT (BZ * TZ)      // 4096
#define N_QKV (3 * CZ)       // 3072
#define KD CZ                // 1024
#define BK 32                // K per stage
#define NST (KD / BK)        // 32 stages

// Scratch (allocation-free rule: __device__ globals)
__device__ float g_q[BZ * HH * TZ * DD];
__device__ float g_k[BZ * HH * TZ * DD];
__device__ float g_v[BZ * HH * TZ * DD];
__device__ float g_y[BZ * TZ * CZ];

// ---------------------------------------------------------------------------
// Portable PTX helpers (no arch-specific ISA: harness targets sm_103 plain)
// ---------------------------------------------------------------------------
__device__ __forceinline__ uint32_t f2tf32(float f) {
    uint32_t r;
    asm("cvt.rna.tf32.f32 %0, %1;" : "=r"(r) : "f"(f));
    return r;
}
__device__ __forceinline__ uint32_t smem_u32(const void* p) {
    uint32_t a;
    asm("{ .reg .u64 t; cvta.to.shared.u64 t, %1; cvt.u32.u64 %0, t; }"
        : "=r"(a) : "l"(p));
    return a;
}
#define SWZ(x) ((uint32_t)(x) ^ ((((uint32_t)(x)) >> 3) & 0x70))

__device__ __forceinline__ void ldsm4(uint32_t* r, uint32_t addr) {
    asm volatile("ldmatrix.sync.aligned.m8n8.x4.shared.b16 {%0,%1,%2,%3}, [%4];"
                 : "=r"(r[0]), "=r"(r[1]), "=r"(r[2]), "=r"(r[3]) : "r"(addr));
}
__device__ __forceinline__ void mma8(float* c, const uint32_t* a,
                                     uint32_t b0, uint32_t b1) {
    asm volatile(
        "mma.sync.aligned.m16n8k8.row.col.f32.tf32.tf32.f32 "
        "{%0,%1,%2,%3}, {%4,%5,%6,%7}, {%8,%9}, {%0,%1,%2,%3};"
        : "+f"(c[0]), "+f"(c[1]), "+f"(c[2]), "+f"(c[3])
        : "r"(a[0]), "r"(a[1]), "r"(a[2]), "r"(a[3]), "r"(b0), "r"(b1));
}

// SMEM byte offsets (dynamic, 64KB): A tiles 128x32 f32, B tiles 128(n)x32(k)
#define AOFF(buf) ((buf) * 16384)
#define BOFF(buf) (32768 + (buf) * 16384)
#define SMEM_BYTES 65536

// ---------------------------------------------------------------------------
// tf32 mma.sync GEMM: C[M,N] = A[M,K=1024] * B[K,N] + bias[N]
// 128x128 tile, BK=32, 256 threads, warp grid 2x4 (warp tile 64x32).
// EPI=1: scatter epilogue into g_q/g_k/g_v ([B,H,T,D]); EPI=0: row-major.
// ---------------------------------------------------------------------------
template <int EPI>
__global__ void __launch_bounds__(256) mma_gemm(
    const float* __restrict__ A, const float* __restrict__ Bm,
    const float* __restrict__ bias, float* __restrict__ Cout, int N)
{
    extern __shared__ char smem[];
    const uint32_t sbase = smem_u32(smem);
    const int tid = threadIdx.x;
    const int lane = tid & 31;
    const int wid = tid >> 5;
    const int bm = blockIdx.y * 128;
    const int bn = blockIdx.x * 128;
    const int wm = (wid >> 2) * 64;    // 0 or 64
    const int wn = (wid & 3) * 32;     // 0,32,64,96

    // ldmatrix per-lane address components
    const int a_r = lane & 15;         // row within 16-row m-tile
    const int a_c = lane >> 4;         // +0/+1 16B chunk (k +0/+4)
    const int b_r = ((lane >> 4) & 1) * 8 + (lane & 7);  // n row within 16
    const int b_c = (lane >> 3) & 1;   // k chunk

    float acc[4][4][4];
#pragma unroll
    for (int i = 0; i < 4; i++)
#pragma unroll
        for (int j = 0; j < 4; j++)
#pragma unroll
            for (int e = 0; e < 4; e++) acc[i][j][e] = 0.f;

    float4 av[4];
    float bv[16];

    auto ldg_stage = [&](int kt) {
        const float* ap = A + (size_t)bm * KD + kt * BK;
#pragma unroll
        for (int i = 0; i < 4; i++) {
            const int idx = i * 256 + tid;
            const int row = idx >> 3, c4 = idx & 7;
            av[i] = *(const float4*)(ap + (size_t)row * KD + c4 * 4);
        }
        const float* bp = Bm + (size_t)(kt * BK) * N + bn;
#pragma unroll
        for (int j = 0; j < 4; j++) {
            const int idx = j * 256 + tid;
            const int n = idx & 127, k4 = idx >> 7;
#pragma unroll
            for (int e = 0; e < 4; e++)
                bv[j * 4 + e] = bp[(size_t)(k4 * 4 + e) * N + n];
        }
    };
    auto sts_stage = [&](int buf) {
#pragma unroll
        for (int i = 0; i < 4; i++) {
            const int idx = i * 256 + tid;
            const int row = idx >> 3, c4 = idx & 7;
            uint4 t;
            t.x = f2tf32(av[i].x); t.y = f2tf32(av[i].y);
            t.z = f2tf32(av[i].z); t.w = f2tf32(av[i].w);
            *(uint4*)(smem + AOFF(buf) + SWZ(row * 128 + c4 * 16)) = t;
        }
#pragma unroll
        for (int j = 0; j < 4; j++) {
            const int idx = j * 256 + tid;
            const int n = idx & 127, k4 = idx >> 7;
            uint4 t;
            t.x = f2tf32(bv[j * 4 + 0]); t.y = f2tf32(bv[j * 4 + 1]);
            t.z = f2tf32(bv[j * 4 + 2]); t.w = f2tf32(bv[j * 4 + 3]);
            *(uint4*)(smem + BOFF(buf) + SWZ(n * 128 + k4 * 16)) = t;
        }
    };
    auto compute = [&](int buf) {
        const uint32_t abase = sbase + AOFF(buf);
        const uint32_t bbase = sbase + BOFF(buf);
#pragma unroll
        for (int ks = 0; ks < 4; ks++) {
            uint32_t af[4][4];
#pragma unroll
            for (int mt = 0; mt < 4; mt++)
                ldsm4(af[mt],
                      abase + SWZ((wm + mt * 16 + a_r) * 128 + (ks * 2 + a_c) * 16));
            uint32_t bf[2][4];
#pragma unroll
            for (int pt = 0; pt < 2; pt++)
                ldsm4(bf[pt],
                      bbase + SWZ((wn + pt * 16 + b_r) * 128 + (ks * 2 + b_c) * 16));
#pragma unroll
            for (int mt = 0; mt < 4; mt++)
#pragma unroll
                for (int nt = 0; nt < 4; nt++) {
                    const uint32_t* bb = bf[nt >> 1];
                    const uint32_t b0 = (nt & 1) ? bb[2] : bb[0];
                    const uint32_t b1 = (nt & 1) ? bb[3] : bb[1];
                    mma8(acc[mt][nt], af[mt], b0, b1);
                }
        }
    };

    ldg_stage(0);
    sts_stage(0);
    __syncthreads();

    for (int kt = 0; kt < NST; kt++) {
        const int cur = kt & 1;
        if (kt + 1 < NST) ldg_stage(kt + 1);   // LDGs in flight over compute
        compute(cur);
        if (kt + 1 < NST) sts_stage(cur ^ 1);
        __syncthreads();
    }

    // Epilogue straight from accumulators
    const int gid = lane >> 2, tig = lane & 3;
#pragma unroll
    for (int nt = 0; nt < 4; nt++) {
        const int col = bn + wn + nt * 8 + tig * 2;
        const float bi0 = bias[col], bi1 = bias[col + 1];
#pragma unroll
        for (int mt = 0; mt < 4; mt++) {
            const int r0 = bm + wm + mt * 16 + gid;
            const int r1 = r0 + 8;
            float2 v0 = {acc[mt][nt][0] + bi0, acc[mt][nt][1] + bi1};
            float2 v1 = {acc[mt][nt][2] + bi0, acc[mt][nt][3] + bi1};
            if (EPI == 1) {
                const int sel = col >> 10;
                const int cc = col & 1023;
                const int h = cc >> 6, d = cc & 63;
                float* dst = (sel == 0) ? g_q : (sel == 1) ? g_k : g_v;
                const int b0i = r0 >> 11, t0 = r0 & (TZ - 1);
                const int b1i = r1 >> 11, t1 = r1 & (TZ - 1);
                *(float2*)&dst[(((size_t)(b0i * HH + h)) * TZ + t0) * DD + d] = v0;
                *(float2*)&dst[(((size_t)(b1i * HH + h)) * TZ + t1) * DD + d] = v1;
            } else {
                *(float2*)&Cout[(size_t)r0 * N + col] = v0;
                *(float2*)&Cout[(size_t)r1 * N + col] = v1;
            }
        }
    }
}

// ---------------------------------------------------------------------------
// Causal flash attention, fp32 scalar (unchanged — passed R1).
// ---------------------------------------------------------------------------
#define BQ 64
#define BKT 64

__global__ __launch_bounds__(64) void attn_kernel()
{
    __shared__ float Ks[BKT][DD];
    __shared__ float Vs[BKT][DD];

    const int tid = threadIdx.x;
    const int q0 = blockIdx.x * BQ;
    const int h  = blockIdx.y;
    const int b  = blockIdx.z;

    const size_t base = ((size_t)(b * HH + h)) * TZ * DD;
    const float* qb = g_q + base;
    const float* kb = g_k + base;
    const float* vb = g_v + base;

    const int q = q0 + tid;

    float qr[DD];
#pragma unroll
    for (int d = 0; d < DD; d++) qr[d] = qb[(size_t)q * DD + d] * 0.125f;

    float acc[DD];
#pragma unroll
    for (int d = 0; d < DD; d++) acc[d] = 0.f;
    float mmax = -INFINITY, lsum = 0.f;

    const int nkt = q0 / BKT + 1;
    for (int kt = 0; kt < nkt; kt++) {
        __syncthreads();
#pragma unroll
        for (int i = 0; i < 16; i++) {
            const int idx = i * 64 + tid;
            const int row = idx >> 4;
            const int col = (idx & 15) * 4;
            *(float4*)&Ks[row][col] =
                *(const float4*)&kb[((size_t)(kt * BKT + row)) * DD + col];
            *(float4*)&Vs[row][col] =
                *(const float4*)&vb[((size_t)(kt * BKT + row)) * DD + col];
        }
        __syncthreads();

        const int jmax = (kt == nkt - 1) ? tid : (BKT - 1);
        for (int j = 0; j <= jmax; j++) {
            float s = 0.f;
#pragma unroll
            for (int d4 = 0; d4 < DD; d4 += 4) {
                float4 kv = *(const float4*)&Ks[j][d4];
                s += qr[d4] * kv.x + qr[d4 + 1] * kv.y +
                     qr[d4 + 2] * kv.z + qr[d4 + 3] * kv.w;
            }
            if (s > mmax) {
                const float corr = __expf(mmax - s);
                lsum = lsum * corr + 1.0f;
#pragma unroll
                for (int d4 = 0; d4 < DD; d4 += 4) {
                    float4 vv = *(const float4*)&Vs[j][d4];
                    acc[d4]     = acc[d4]     * corr + vv.x;
                    acc[d4 + 1] = acc[d4 + 1] * corr + vv.y;
                    acc[d4 + 2] = acc[d4 + 2] * corr + vv.z;
                    acc[d4 + 3] = acc[d4 + 3] * corr + vv.w;
                }
                mmax = s;
            } else {
                const float p = __expf(s - mmax);
                lsum += p;
#pragma unroll
                for (int d4 = 0; d4 < DD; d4 += 4) {
                    float4 vv = *(const float4*)&Vs[j][d4];
                    acc[d4]     += p * vv.x;
                    acc[d4 + 1] += p * vv.y;
                    acc[d4 + 2] += p * vv.z;
                    acc[d4 + 3] += p * vv.w;
                }
            }
        }
    }

    const float inv = 1.0f / lsum;
#pragma unroll
    for (int d = 0; d < DD; d++)
        g_y[((size_t)(b * TZ + q)) * CZ + h * DD + d] = acc[d] * inv;
}

// ---------------------------------------------------------------------------
extern "C" void kernel_launch(void* const* d_in, const int* in_sizes, int n_in,
                              void* d_out, int out_size)
{
    const float* x      = (const float*)d_in[0];
    const float* w_attn = (const float*)d_in[1];
    const float* b_attn = (const float*)d_in[2];
    const float* w_proj = (const float*)d_in[3];
    const float* b_proj = (const float*)d_in[4];
    float* out = (float*)d_out;

    void* y_ptr = nullptr;
    cudaGetSymbolAddress(&y_ptr, g_y);

    cudaFuncSetAttribute(mma_gemm<1>, cudaFuncAttributeMaxDynamicSharedMemorySize, SMEM_BYTES);
    cudaFuncSetAttribute(mma_gemm<0>, cudaFuncAttributeMaxDynamicSharedMemorySize, SMEM_BYTES);

    // 1) QKV GEMM (tf32 mma.sync): [4096,1024]x[1024,3072] -> q/k/v [B,H,T,D]
    mma_gemm<1><<<dim3(N_QKV / 128, M_TOT / 128), 256, SMEM_BYTES>>>(
        x, w_attn, b_attn, nullptr, N_QKV);

    // 2) Causal attention -> g_y [B,T,C]
    attn_kernel<<<dim3(TZ / BQ, HH, BZ), 64>>>();

    // 3) Proj GEMM (tf32 mma.sync): [4096,1024]x[1024,1024] -> d_out
    mma_gemm<0><<<dim3(CZ / 128, M_TOT / 128), 256, SMEM_BYTES>>>(
        (const float*)y_ptr, w_proj, b_proj, out, CZ);
}

// round 4
// speedup vs baseline: 4.6364x; 2.7278x over previous
#include <cuda_runtime.h>
#include <cstdint>
#include <math.h>

#define BZ 2
#define TZ 2048
#define CZ 1024
#define HH 16
#define DD 64
#define M_TOT (BZ * TZ)      // 4096
#define N_QKV (3 * CZ)       // 3072
#define KD CZ                // 1024
#define BK 32                // K per GEMM stage
#define NST (KD / BK)        // 32 stages

// Scratch (allocation-free rule: __device__ globals)
__device__ float g_q[BZ * HH * TZ * DD];   // [B,H,T,D]
__device__ float g_k[BZ * HH * TZ * DD];   // [B,H,T,D]
__device__ float g_v[BZ * HH * TZ * DD];   // [B,H,D,T]  (TRANSPOSED)
__device__ float g_y[BZ * TZ * CZ];

// ---------------------------------------------------------------------------
// Portable PTX helpers (harness targets plain sm_103: no tcgen05)
// ---------------------------------------------------------------------------
__device__ __forceinline__ uint32_t f2tf32(float f) {
    uint32_t r;
    asm("cvt.rna.tf32.f32 %0, %1;" : "=r"(r) : "f"(f));
    return r;
}
__device__ __forceinline__ uint32_t smem_u32(const void* p) {
    uint32_t a;
    asm("{ .reg .u64 t; cvta.to.shared.u64 t, %1; cvt.u32.u64 %0, t; }"
        : "=r"(a) : "l"(p));
    return a;
}
#define SWZ(x) ((uint32_t)(x) ^ ((((uint32_t)(x)) >> 3) & 0x70))

__device__ __forceinline__ void ldsm4(uint32_t* r, uint32_t addr) {
    asm volatile("ldmatrix.sync.aligned.m8n8.x4.shared.b16 {%0,%1,%2,%3}, [%4];"
                 : "=r"(r[0]), "=r"(r[1]), "=r"(r[2]), "=r"(r[3]) : "r"(addr));
}
__device__ __forceinline__ void mma8(float* c, const uint32_t* a,
                                     uint32_t b0, uint32_t b1) {
    asm volatile(
        "mma.sync.aligned.m16n8k8.row.col.f32.tf32.tf32.f32 "
        "{%0,%1,%2,%3}, {%4,%5,%6,%7}, {%8,%9}, {%0,%1,%2,%3};"
        : "+f"(c[0]), "+f"(c[1]), "+f"(c[2]), "+f"(c[3])
        : "r"(a[0]), "r"(a[1]), "r"(a[2]), "r"(a[3]), "r"(b0), "r"(b1));
}
__device__ __forceinline__ void cvt4(uint32_t* r) {
    r[0] = f2tf32(__uint_as_float(r[0]));
    r[1] = f2tf32(__uint_as_float(r[1]));
    r[2] = f2tf32(__uint_as_float(r[2]));
    r[3] = f2tf32(__uint_as_float(r[3]));
}
__device__ __forceinline__ void cpasync16(uint32_t dst, const void* src) {
    asm volatile("cp.async.cg.shared.global [%0], [%1], 16;"
                 :: "r"(dst), "l"(src));
}
#define CP_COMMIT() asm volatile("cp.async.commit_group;")
#define CP_WAIT0()  asm volatile("cp.async.wait_group 0;")

// ===========================================================================
// GEMM (from R3, validated): C[M,N] = A[M,K=1024] * B[K,N] + bias[N]
// ===========================================================================
#define AOFF(buf) ((buf) * 16384)
#define BOFF(buf) (32768 + (buf) * 16384)
#define GEMM_SMEM 65536

template <int EPI>
__global__ void __launch_bounds__(256) mma_gemm(
    const float* __restrict__ A, const float* __restrict__ Bm,
    const float* __restrict__ bias, float* __restrict__ Cout, int N)
{
    extern __shared__ char smem[];
    const uint32_t sbase = smem_u32(smem);
    const int tid = threadIdx.x;
    const int lane = tid & 31;
    const int wid = tid >> 5;
    const int bm = blockIdx.y * 128;
    const int bn = blockIdx.x * 128;
    const int wm = (wid >> 2) * 64;
    const int wn = (wid & 3) * 32;

    const int a_r = lane & 15;
    const int a_c = lane >> 4;
    const int b_r = ((lane >> 4) & 1) * 8 + (lane & 7);
    const int b_c = (lane >> 3) & 1;

    float acc[4][4][4];
#pragma unroll
    for (int i = 0; i < 4; i++)
#pragma unroll
        for (int j = 0; j < 4; j++)
#pragma unroll
            for (int e = 0; e < 4; e++) acc[i][j][e] = 0.f;

    float4 av[4];
    float bv[16];

    auto ldg_stage = [&](int kt) {
        const float* ap = A + (size_t)bm * KD + kt * BK;
#pragma unroll
        for (int i = 0; i < 4; i++) {
            const int idx = i * 256 + tid;
            const int row = idx >> 3, c4 = idx & 7;
            av[i] = *(const float4*)(ap + (size_t)row * KD + c4 * 4);
        }
        const float* bp = Bm + (size_t)(kt * BK) * N + bn;
#pragma unroll
        for (int j = 0; j < 4; j++) {
            const int idx = j * 256 + tid;
            const int n = idx & 127, k4 = idx >> 7;
#pragma unroll
            for (int e = 0; e < 4; e++)
                bv[j * 4 + e] = bp[(size_t)(k4 * 4 + e) * N + n];
        }
    };
    auto sts_stage = [&](int buf) {
#pragma unroll
        for (int i = 0; i < 4; i++) {
            const int idx = i * 256 + tid;
            const int row = idx >> 3, c4 = idx & 7;
            uint4 t;
            t.x = f2tf32(av[i].x); t.y = f2tf32(av[i].y);
            t.z = f2tf32(av[i].z); t.w = f2tf32(av[i].w);
            *(uint4*)(smem + AOFF(buf) + SWZ(row * 128 + c4 * 16)) = t;
        }
#pragma unroll
        for (int j = 0; j < 4; j++) {
            const int idx = j * 256 + tid;
            const int n = idx & 127, k4 = idx >> 7;
            uint4 t;
            t.x = f2tf32(bv[j * 4 + 0]); t.y = f2tf32(bv[j * 4 + 1]);
            t.z = f2tf32(bv[j * 4 + 2]); t.w = f2tf32(bv[j * 4 + 3]);
            *(uint4*)(smem + BOFF(buf) + SWZ(n * 128 + k4 * 16)) = t;
        }
    };
    auto compute = [&](int buf) {
        const uint32_t abase = sbase + AOFF(buf);
        const uint32_t bbase = sbase + BOFF(buf);
#pragma unroll
        for (int ks = 0; ks < 4; ks++) {
            uint32_t af[4][4];
#pragma unroll
            for (int mt = 0; mt < 4; mt++)
                ldsm4(af[mt],
                      abase + SWZ((wm + mt * 16 + a_r) * 128 + (ks * 2 + a_c) * 16));
            uint32_t bf[2][4];
#pragma unroll
            for (int pt = 0; pt < 2; pt++)
                ldsm4(bf[pt],
                      bbase + SWZ((wn + pt * 16 + b_r) * 128 + (ks * 2 + b_c) * 16));
#pragma unroll
            for (int mt = 0; mt < 4; mt++)
#pragma unroll
                for (int nt = 0; nt < 4; nt++) {
                    const uint32_t* bb = bf[nt >> 1];
                    const uint32_t b0 = (nt & 1) ? bb[2] : bb[0];
                    const uint32_t b1 = (nt & 1) ? bb[3] : bb[1];
                    mma8(acc[mt][nt], af[mt], b0, b1);
                }
        }
    };

    ldg_stage(0);
    sts_stage(0);
    __syncthreads();

    for (int kt = 0; kt < NST; kt++) {
        const int cur = kt & 1;
        if (kt + 1 < NST) ldg_stage(kt + 1);
        compute(cur);
        if (kt + 1 < NST) sts_stage(cur ^ 1);
        __syncthreads();
    }

    const int gid = lane >> 2, tig = lane & 3;
#pragma unroll
    for (int nt = 0; nt < 4; nt++) {
        const int col = bn + wn + nt * 8 + tig * 2;
        const float bi0 = bias[col], bi1 = bias[col + 1];
#pragma unroll
        for (int mt = 0; mt < 4; mt++) {
            const int r0 = bm + wm + mt * 16 + gid;
            const int r1 = r0 + 8;
            float2 v0 = {acc[mt][nt][0] + bi0, acc[mt][nt][1] + bi1};
            float2 v1 = {acc[mt][nt][2] + bi0, acc[mt][nt][3] + bi1};
            if (EPI == 1) {
                const int sel = col >> 10;
                const int cc = col & 1023;
                const int h = cc >> 6, d = cc & 63;
                const int b0i = r0 >> 11, t0 = r0 & (TZ - 1);
                const int b1i = r1 >> 11, t1 = r1 & (TZ - 1);
                if (sel == 2) {  // V: transposed [B,H,D,T]
                    const size_t p0 = ((size_t)(b0i * HH + h) * DD + d) * TZ + t0;
                    const size_t p1 = ((size_t)(b1i * HH + h) * DD + d) * TZ + t1;
                    g_v[p0] = v0.x; g_v[p0 + TZ] = v0.y;
                    g_v[p1] = v1.x; g_v[p1 + TZ] = v1.y;
                } else {
                    float* dst = (sel == 0) ? g_q : g_k;
                    *(float2*)&dst[(((size_t)(b0i * HH + h)) * TZ + t0) * DD + d] = v0;
                    *(float2*)&dst[(((size_t)(b1i * HH + h)) * TZ + t1) * DD + d] = v1;
                }
            } else {
                *(float2*)&Cout[(size_t)r0 * N + col] = v0;
                *(float2*)&Cout[(size_t)r1 * N + col] = v1;
            }
        }
    }
}

// ===========================================================================
// Flash attention with tf32 mma.sync.
// Block: 64 queries for one (b,h); 4 warps x 16 rows; K-tiles of 64.
// SMEM (dynamic 96KB):
//   Qs  @0      : 64x64 tf32, 2 k-chunks of 64x128B (16KB)
//   Ks  @16384  : 2 bufs x 16KB, rows=key, k-chunks over dim
//   Vs  @49152  : 2 bufs x 16KB, rows=dim, k-chunks over key (from g_v [d][t])
//   Ps  @81920  : per-warp 4KB staging (16 rows x 64 keys tf32, 2 chunks)
// ===========================================================================
#define ATT_SMEM 98304

__global__ void __launch_bounds__(128) attn_mma()
{
    extern __shared__ char smem[];
    const uint32_t sb = smem_u32(smem);
    const int tid = threadIdx.x, lane = tid & 31, wid = tid >> 5;
    const int bx = blockIdx.x;
    const int h = blockIdx.y, b = blockIdx.z;
    const int q0 = bx * 64;
    const size_t bh = (size_t)(b * HH + h);
    const float* qg = g_q + bh * TZ * DD;
    const float* kg = g_k + bh * TZ * DD;
    const float* vg = g_v + bh * DD * TZ;   // [d][t]

    const uint32_t QS = 0, KS0 = 16384, VS0 = 49152;
    const uint32_t PSo = 81920 + wid * 4096;

    const int a_r = lane & 15;
    const int a_c = lane >> 4;
    const int b_r = ((lane >> 4) & 1) * 8 + (lane & 7);
    const int b_c = (lane >> 3) & 1;
    const int gid = lane >> 2, tig = lane & 3;

    // Q tile: load, scale by 1/sqrt(D), convert to tf32
    {
        const float* qp = qg + (size_t)q0 * DD;
#pragma unroll
        for (int i = 0; i < 8; i++) {
            const int idx = i * 128 + tid;
            const int row = idx >> 4, c16 = idx & 15;
            float4 v = *(const float4*)(qp + row * 64 + c16 * 4);
            uint4 t;
            t.x = f2tf32(v.x * 0.125f); t.y = f2tf32(v.y * 0.125f);
            t.z = f2tf32(v.z * 0.125f); t.w = f2tf32(v.w * 0.125f);
            *(uint4*)(smem + QS + (c16 >> 3) * 8192 +
                      SWZ(row * 128 + (c16 & 7) * 16)) = t;
        }
    }

    auto load_kv = [&](int kt, int buf) {
        const float* kp = kg + (size_t)(kt * 64) * DD;
#pragma unroll
        for (int i = 0; i < 8; i++) {
            const int idx = i * 128 + tid;
            const int key = idx >> 4, c16 = idx & 15;
            cpasync16(sb + KS0 + buf * 16384 + (c16 >> 3) * 8192 +
                          SWZ(key * 128 + (c16 & 7) * 16),
                      kp + key * 64 + c16 * 4);
        }
        const float* vp = vg + kt * 64;
#pragma unroll
        for (int i = 0; i < 8; i++) {
            const int idx = i * 128 + tid;
            const int d = idx >> 4, k16 = idx & 15;
            cpasync16(sb + VS0 + buf * 16384 + (k16 >> 3) * 8192 +
                          SWZ(d * 128 + (k16 & 7) * 16),
                      vp + (size_t)d * TZ + k16 * 4);
        }
    };

    const int nkt = bx + 1;
    load_kv(0, 0);
    CP_COMMIT();

    float oacc[8][4];
#pragma unroll
    for (int nt = 0; nt < 8; nt++)
#pragma unroll
        for (int e = 0; e < 4; e++) oacc[nt][e] = 0.f;
    float m0 = -1e30f, m1 = -1e30f, l0 = 0.f, l1 = 0.f;

    for (int kt = 0; kt < nkt; kt++) {
        const int cur = kt & 1;
        CP_WAIT0();
        __syncthreads();
        if (kt + 1 < nkt) { load_kv(kt + 1, cur ^ 1); CP_COMMIT(); }

        // ---- S = Q K^T (warp rows: wid*16..+16, all 64 keys) ----
        float sacc[8][4];
#pragma unroll
        for (int nt = 0; nt < 8; nt++)
#pragma unroll
            for (int e = 0; e < 4; e++) sacc[nt][e] = 0.f;

        const uint32_t ksb = sb + KS0 + cur * 16384;
#pragma unroll
        for (int ch = 0; ch < 2; ch++)
#pragma unroll
            for (int ks = 0; ks < 4; ks++) {
                uint32_t af[4];
                ldsm4(af, sb + QS + ch * 8192 +
                          SWZ((wid * 16 + a_r) * 128 + (ks * 2 + a_c) * 16));
                uint32_t bf[4][4];
#pragma unroll
                for (int pt = 0; pt < 4; pt++) {
                    ldsm4(bf[pt], ksb + ch * 8192 +
                              SWZ((pt * 16 + b_r) * 128 + (ks * 2 + b_c) * 16));
                    cvt4(bf[pt]);
                }
#pragma unroll
                for (int nt = 0; nt < 8; nt++) {
                    const uint32_t* bb = bf[nt >> 1];
                    mma8(sacc[nt], af, (nt & 1) ? bb[2] : bb[0],
                         (nt & 1) ? bb[3] : bb[1]);
                }
            }

        // ---- causal mask on diagonal tile ----
        if (kt == bx) {
            const int row0 = wid * 16 + gid;
#pragma unroll
            for (int nt = 0; nt < 8; nt++) {
                const int col = nt * 8 + tig * 2;
                if (col     > row0)     sacc[nt][0] = -1e30f;
                if (col + 1 > row0)     sacc[nt][1] = -1e30f;
                if (col     > row0 + 8) sacc[nt][2] = -1e30f;
                if (col + 1 > row0 + 8) sacc[nt][3] = -1e30f;
            }
        }

        // ---- online softmax ----
        float mx0 = -1e30f, mx1 = -1e30f;
#pragma unroll
        for (int nt = 0; nt < 8; nt++) {
            mx0 = fmaxf(mx0, fmaxf(sacc[nt][0], sacc[nt][1]));
            mx1 = fmaxf(mx1, fmaxf(sacc[nt][2], sacc[nt][3]));
        }
        mx0 = fmaxf(mx0, __shfl_xor_sync(0xffffffffu, mx0, 1));
        mx0 = fmaxf(mx0, __shfl_xor_sync(0xffffffffu, mx0, 2));
        mx1 = fmaxf(mx1, __shfl_xor_sync(0xffffffffu, mx1, 1));
        mx1 = fmaxf(mx1, __shfl_xor_sync(0xffffffffu, mx1, 2));
        const float mn0 = fmaxf(m0, mx0), mn1 = fmaxf(m1, mx1);
        const float c0 = __expf(m0 - mn0), c1 = __expf(m1 - mn1);
        m0 = mn0; m1 = mn1;
        float s0 = 0.f, s1 = 0.f;
#pragma unroll
        for (int nt = 0; nt < 8; nt++) {
            sacc[nt][0] = __expf(sacc[nt][0] - m0);
            sacc[nt][1] = __expf(sacc[nt][1] - m0);
            sacc[nt][2] = __expf(sacc[nt][2] - m1);
            sacc[nt][3] = __expf(sacc[nt][3] - m1);
            s0 += sacc[nt][0] + sacc[nt][1];
            s1 += sacc[nt][2] + sacc[nt][3];
        }
        s0 += __shfl_xor_sync(0xffffffffu, s0, 1);
        s0 += __shfl_xor_sync(0xffffffffu, s0, 2);
        s1 += __shfl_xor_sync(0xffffffffu, s1, 1);
        s1 += __shfl_xor_sync(0xffffffffu, s1, 2);
        l0 = l0 * c0 + s0;
        l1 = l1 * c1 + s1;
#pragma unroll
        for (int nt = 0; nt < 8; nt++) {
            oacc[nt][0] *= c0; oacc[nt][1] *= c0;
            oacc[nt][2] *= c1; oacc[nt][3] *= c1;
        }

        // ---- stage P (tf32) to per-warp SMEM as A-operand ----
#pragma unroll
        for (int nt = 0; nt < 8; nt++) {
            const int col = nt * 8 + tig * 2;
            const uint32_t cb = (col >> 5) * 2048;
            uint2 p0, p1;
            p0.x = f2tf32(sacc[nt][0]); p0.y = f2tf32(sacc[nt][1]);
            p1.x = f2tf32(sacc[nt][2]); p1.y = f2tf32(sacc[nt][3]);
            *(uint2*)(smem + PSo + cb + SWZ(gid * 128 + (col & 31) * 4)) = p0;
            *(uint2*)(smem + PSo + cb + SWZ((gid + 8) * 128 + (col & 31) * 4)) = p1;
        }
        __syncwarp();

        // ---- O += P V ----
        const uint32_t vsb = sb + VS0 + cur * 16384;
#pragma unroll
        for (int ch = 0; ch < 2; ch++)
#pragma unroll
            for (int ks = 0; ks < 4; ks++) {
                uint32_t af[4];
                ldsm4(af, sb + PSo + ch * 2048 +
                          SWZ(a_r * 128 + (ks * 2 + a_c) * 16));
                uint32_t bf[4][4];
#pragma unroll
                for (int pt = 0; pt < 4; pt++) {
                    ldsm4(bf[pt], vsb + ch * 8192 +
                              SWZ((pt * 16 + b_r) * 128 + (ks * 2 + b_c) * 16));
                    cvt4(bf[pt]);
                }
#pragma unroll
                for (int nt = 0; nt < 8; nt++) {
                    const uint32_t* bb = bf[nt >> 1];
                    mma8(oacc[nt], af, (nt & 1) ? bb[2] : bb[0],
                         (nt & 1) ? bb[3] : bb[1]);
                }
            }
        __syncthreads();  // all warps done with cur K/V before it's reloaded
    }

    // ---- write O / l to g_y [B,T,C] ----
    const float i0 = 1.0f / l0, i1 = 1.0f / l1;
    float* yp = g_y + ((size_t)b * TZ + q0 + wid * 16) * CZ + h * DD;
#pragma unroll
    for (int nt = 0; nt < 8; nt++) {
        const int d = nt * 8 + tig * 2;
        float2 v0 = {oacc[nt][0] * i0, oacc[nt][1] * i0};
        float2 v1 = {oacc[nt][2] * i1, oacc[nt][3] * i1};
        *(float2*)(yp + (size_t)gid * CZ + d) = v0;
        *(float2*)(yp + (size_t)(gid + 8) * CZ + d) = v1;
    }
}

// ---------------------------------------------------------------------------
extern "C" void kernel_launch(void* const* d_in, const int* in_sizes, int n_in,
                              void* d_out, int out_size)
{
    const float* x      = (const float*)d_in[0];
    const float* w_attn = (const float*)d_in[1];
    const float* b_attn = (const float*)d_in[2];
    const float* w_proj = (const float*)d_in[3];
    const float* b_proj = (const float*)d_in[4];
    float* out = (float*)d_out;

    void* y_ptr = nullptr;
    cudaGetSymbolAddress(&y_ptr, g_y);

    cudaFuncSetAttribute(mma_gemm<1>, cudaFuncAttributeMaxDynamicSharedMemorySize, GEMM_SMEM);
    cudaFuncSetAttribute(mma_gemm<0>, cudaFuncAttributeMaxDynamicSharedMemorySize, GEMM_SMEM);
    cudaFuncSetAttribute(attn_mma, cudaFuncAttributeMaxDynamicSharedMemorySize, ATT_SMEM);

    // 1) QKV GEMM -> q/k [B,H,T,D], v [B,H,D,T]
    mma_gemm<1><<<dim3(N_QKV / 128, M_TOT / 128), 256, GEMM_SMEM>>>(
        x, w_attn, b_attn, nullptr, N_QKV);

    // 2) Flash attention (tf32 mma) -> g_y [B,T,C]
    attn_mma<<<dim3(TZ / 64, HH, BZ), 128, ATT_SMEM>>>();

    // 3) Proj GEMM -> d_out
    mma_gemm<0><<<dim3(CZ / 128, M_TOT / 128), 256, GEMM_SMEM>>>(
        (const float*)y_ptr, w_proj, b_proj, out, CZ);
}

// round 5
// speedup vs baseline: 5.1054x; 1.1012x over previous
#include <cuda_runtime.h>
#include <cstdint>
#include <math.h>

#define BZ 2
#define TZ 2048
#define CZ 1024
#define HH 16
#define DD 64
#define M_TOT (BZ * TZ)      // 4096
#define N_QKV (3 * CZ)       // 3072
#define KD CZ                // 1024
#define BK 32                // K per GEMM stage
#define NST (KD / BK)        // 32 stages

// Scratch (allocation-free rule: __device__ globals)
__device__ float g_q[BZ * HH * TZ * DD];       // [B,H,T,D]
__device__ float g_k[BZ * HH * TZ * DD];       // [B,H,T,D]
__device__ float g_v[BZ * HH * TZ * DD];       // [B,H,D,T] (TRANSPOSED)
__device__ float g_y[BZ * TZ * CZ];            // tf32-valued floats
__device__ uint32_t g_xa[M_TOT * KD];          // x  as tf32 [M][K]
__device__ uint32_t g_wa[N_QKV * KD];          // w_attn^T tf32 [N][K]
__device__ uint32_t g_wp[CZ * KD];             // w_proj^T tf32 [N][K]

// ---------------------------------------------------------------------------
// Portable PTX helpers (harness targets plain sm_103: no tcgen05)
// ---------------------------------------------------------------------------
__device__ __forceinline__ uint32_t f2tf32(float f) {
    uint32_t r;
    asm("cvt.rna.tf32.f32 %0, %1;" : "=r"(r) : "f"(f));
    return r;
}
__device__ __forceinline__ uint32_t smem_u32(const void* p) {
    uint32_t a;
    asm("{ .reg .u64 t; cvta.to.shared.u64 t, %1; cvt.u32.u64 %0, t; }"
        : "=r"(a) : "l"(p));
    return a;
}
#define SWZ(x) ((uint32_t)(x) ^ ((((uint32_t)(x)) >> 3) & 0x70))

__device__ __forceinline__ void ldsm4(uint32_t* r, uint32_t addr) {
    asm volatile("ldmatrix.sync.aligned.m8n8.x4.shared.b16 {%0,%1,%2,%3}, [%4];"
                 : "=r"(r[0]), "=r"(r[1]), "=r"(r[2]), "=r"(r[3]) : "r"(addr));
}
__device__ __forceinline__ void mma8(float* c, const uint32_t* a,
                                     uint32_t b0, uint32_t b1) {
    asm volatile(
        "mma.sync.aligned.m16n8k8.row.col.f32.tf32.tf32.f32 "
        "{%0,%1,%2,%3}, {%4,%5,%6,%7}, {%8,%9}, {%0,%1,%2,%3};"
        : "+f"(c[0]), "+f"(c[1]), "+f"(c[2]), "+f"(c[3])
        : "r"(a[0]), "r"(a[1]), "r"(a[2]), "r"(a[3]), "r"(b0), "r"(b1));
}
__device__ __forceinline__ void cvt4(uint32_t* r) {
    r[0] = f2tf32(__uint_as_float(r[0]));
    r[1] = f2tf32(__uint_as_float(r[1]));
    r[2] = f2tf32(__uint_as_float(r[2]));
    r[3] = f2tf32(__uint_as_float(r[3]));
}
__device__ __forceinline__ void cpasync16(uint32_t dst, const void* src) {
    asm volatile("cp.async.cg.shared.global [%0], [%1], 16;"
                 :: "r"(dst), "l"(src));
}
#define CP_COMMIT() asm volatile("cp.async.commit_group;")
#define CP_WAITG(n) asm volatile("cp.async.wait_group %0;" :: "n"(n))
#define CP_WAIT0()  asm volatile("cp.async.wait_group 0;")

// ===========================================================================
// Pre-pass kernels
// ===========================================================================
__global__ void __launch_bounds__(256) cvt_x(const float4* __restrict__ X,
                                             uint4* __restrict__ Xt) {
    const int i = blockIdx.x * 256 + threadIdx.x;
    float4 v = X[i];
    uint4 t;
    t.x = f2tf32(v.x); t.y = f2tf32(v.y); t.z = f2tf32(v.z); t.w = f2tf32(v.w);
    Xt[i] = t;
}

// W [K=1024][N] -> Wt [N][K=1024] tf32
__global__ void __launch_bounds__(256) wtrans(const float* __restrict__ W,
                                              uint32_t* __restrict__ Wt, int N) {
    __shared__ uint32_t t[32][33];
    const int tx = threadIdx.x & 31, ty = threadIdx.x >> 5;
    const int n0 = blockIdx.x * 32, k0 = blockIdx.y * 32;
#pragma unroll
    for (int i = 0; i < 4; i++)
        t[ty + i * 8][tx] = f2tf32(W[(size_t)(k0 + ty + i * 8) * N + n0 + tx]);
    __syncthreads();
#pragma unroll
    for (int i = 0; i < 4; i++)
        Wt[(size_t)(n0 + ty + i * 8) * KD + k0 + tx] = t[tx][ty + i * 8];
}

// ===========================================================================
// tf32 GEMM, 4-stage cp.async pipeline.
// A tf32 [M][K], B tf32 [N][K]. C = A*B^T + bias.
// 128x128 tile, BK=32, 256 threads, warp grid 2x4 (warp tile 64x32).
// EPI=1: scatter to g_q/g_k/g_v (V transposed); EPI=0: row-major store.
// ===========================================================================
#define GEMM_SMEM 131072   // 4 stages x (16KB A + 16KB B)

template <int EPI>
__global__ void __launch_bounds__(256) mma_gemm(
    const uint32_t* __restrict__ A, const uint32_t* __restrict__ Bt,
    const float* __restrict__ bias, float* __restrict__ Cout, int N)
{
    extern __shared__ char smem[];
    const uint32_t sbase = smem_u32(smem);
    const int tid = threadIdx.x;
    const int lane = tid & 31;
    const int wid = tid >> 5;
    const int bm = blockIdx.y * 128;
    const int bn = blockIdx.x * 128;
    const int wm = (wid >> 2) * 64;
    const int wn = (wid & 3) * 32;

    const int a_r = lane & 15;
    const int a_c = lane >> 4;
    const int b_r = ((lane >> 4) & 1) * 8 + (lane & 7);
    const int b_c = (lane >> 3) & 1;

    float acc[4][4][4];
#pragma unroll
    for (int i = 0; i < 4; i++)
#pragma unroll
        for (int j = 0; j < 4; j++)
#pragma unroll
            for (int e = 0; e < 4; e++) acc[i][j][e] = 0.f;

    auto issue_stage = [&](int kt, int buf) {
#pragma unroll
        for (int i = 0; i < 4; i++) {
            const int idx = i * 256 + tid;
            const int r = idx >> 3, c = idx & 7;
            const uint32_t so = SWZ(r * 128 + c * 16);
            cpasync16(sbase + buf * 32768 + so,
                      A + (size_t)(bm + r) * KD + kt * BK + c * 4);
            cpasync16(sbase + buf * 32768 + 16384 + so,
                      Bt + (size_t)(bn + r) * KD + kt * BK + c * 4);
        }
    };

    auto compute = [&](int buf) {
        const uint32_t abase = sbase + buf * 32768;
        const uint32_t bbase = abase + 16384;
#pragma unroll
        for (int ks = 0; ks < 4; ks++) {
            uint32_t af[4][4];
#pragma unroll
            for (int mt = 0; mt < 4; mt++)
                ldsm4(af[mt],
                      abase + SWZ((wm + mt * 16 + a_r) * 128 + (ks * 2 + a_c) * 16));
            uint32_t bf[2][4];
#pragma unroll
            for (int pt = 0; pt < 2; pt++)
                ldsm4(bf[pt],
                      bbase + SWZ((wn + pt * 16 + b_r) * 128 + (ks * 2 + b_c) * 16));
#pragma unroll
            for (int mt = 0; mt < 4; mt++)
#pragma unroll
                for (int nt = 0; nt < 4; nt++) {
                    const uint32_t* bb = bf[nt >> 1];
                    const uint32_t b0 = (nt & 1) ? bb[2] : bb[0];
                    const uint32_t b1 = (nt & 1) ? bb[3] : bb[1];
                    mma8(acc[mt][nt], af[mt], b0, b1);
                }
        }
    };

    issue_stage(0, 0); CP_COMMIT();
    issue_stage(1, 1); CP_COMMIT();
    issue_stage(2, 2); CP_COMMIT();

    for (int kt = 0; kt < NST; kt++) {
        CP_WAITG(2);            // group kt complete -> stage kt resident
        __syncthreads();        // also guards buffer reuse below
        if (kt + 3 < NST) issue_stage(kt + 3, (kt + 3) & 3);
        CP_COMMIT();            // empty group in the tail keeps invariant
        compute(kt & 3);
    }

    const int gid = lane >> 2, tig = lane & 3;
#pragma unroll
    for (int nt = 0; nt < 4; nt++) {
        const int col = bn + wn + nt * 8 + tig * 2;
        const float bi0 = bias[col], bi1 = bias[col + 1];
#pragma unroll
        for (int mt = 0; mt < 4; mt++) {
            const int r0 = bm + wm + mt * 16 + gid;
            const int r1 = r0 + 8;
            float2 v0 = {acc[mt][nt][0] + bi0, acc[mt][nt][1] + bi1};
            float2 v1 = {acc[mt][nt][2] + bi0, acc[mt][nt][3] + bi1};
            if (EPI == 1) {
                const int sel = col >> 10;
                const int cc = col & 1023;
                const int h = cc >> 6, d = cc & 63;
                const int b0i = r0 >> 11, t0 = r0 & (TZ - 1);
                const int b1i = r1 >> 11, t1 = r1 & (TZ - 1);
                if (sel == 2) {  // V transposed [B,H,D,T]
                    const size_t p0 = ((size_t)(b0i * HH + h) * DD + d) * TZ + t0;
                    const size_t p1 = ((size_t)(b1i * HH + h) * DD + d) * TZ + t1;
                    g_v[p0] = v0.x; g_v[p0 + TZ] = v0.y;
                    g_v[p1] = v1.x; g_v[p1 + TZ] = v1.y;
                } else {
                    float* dst = (sel == 0) ? g_q : g_k;
                    *(float2*)&dst[(((size_t)(b0i * HH + h)) * TZ + t0) * DD + d] = v0;
                    *(float2*)&dst[(((size_t)(b1i * HH + h)) * TZ + t1) * DD + d] = v1;
                }
            } else {
                *(float2*)&Cout[(size_t)r0 * N + col] = v0;
                *(float2*)&Cout[(size_t)r1 * N + col] = v1;
            }
        }
    }
}

// ===========================================================================
// Flash attention with tf32 mma.sync (validated R4). 64q/block, 4 warps.
// Epilogue now stores y tf32-rounded so proj GEMM consumes raw bits.
// ===========================================================================
#define ATT_SMEM 98304

__global__ void __launch_bounds__(128) attn_mma()
{
    extern __shared__ char smem[];
    const uint32_t sb = smem_u32(smem);
    const int tid = threadIdx.x, lane = tid & 31, wid = tid >> 5;
    const int bx = blockIdx.x;
    const int h = blockIdx.y, b = blockIdx.z;
    const int q0 = bx * 64;
    const size_t bh = (size_t)(b * HH + h);
    const float* qg = g_q + bh * TZ * DD;
    const float* kg = g_k + bh * TZ * DD;
    const float* vg = g_v + bh * DD * TZ;   // [d][t]

    const uint32_t QS = 0, KS0 = 16384, VS0 = 49152;
    const uint32_t PSo = 81920 + wid * 4096;

    const int a_r = lane & 15;
    const int a_c = lane >> 4;
    const int b_r = ((lane >> 4) & 1) * 8 + (lane & 7);
    const int b_c = (lane >> 3) & 1;
    const int gid = lane >> 2, tig = lane & 3;

    {
        const float* qp = qg + (size_t)q0 * DD;
#pragma unroll
        for (int i = 0; i < 8; i++) {
            const int idx = i * 128 + tid;
            const int row = idx >> 4, c16 = idx & 15;
            float4 v = *(const float4*)(qp + row * 64 + c16 * 4);
            uint4 t;
            t.x = f2tf32(v.x * 0.125f); t.y = f2tf32(v.y * 0.125f);
            t.z = f2tf32(v.z * 0.125f); t.w = f2tf32(v.w * 0.125f);
            *(uint4*)(smem + QS + (c16 >> 3) * 8192 +
                      SWZ(row * 128 + (c16 & 7) * 16)) = t;
        }
    }

    auto load_kv = [&](int kt, int buf) {
        const float* kp = kg + (size_t)(kt * 64) * DD;
#pragma unroll
        for (int i = 0; i < 8; i++) {
            const int idx = i * 128 + tid;
            const int key = idx >> 4, c16 = idx & 15;
            cpasync16(sb + KS0 + buf * 16384 + (c16 >> 3) * 8192 +
                          SWZ(key * 128 + (c16 & 7) * 16),
                      kp + key * 64 + c16 * 4);
        }
        const float* vp = vg + kt * 64;
#pragma unroll
        for (int i = 0; i < 8; i++) {
            const int idx = i * 128 + tid;
            const int d = idx >> 4, k16 = idx & 15;
            cpasync16(sb + VS0 + buf * 16384 + (k16 >> 3) * 8192 +
                          SWZ(d * 128 + (k16 & 7) * 16),
                      vp + (size_t)d * TZ + k16 * 4);
        }
    };

    const int nkt = bx + 1;
    load_kv(0, 0);
    CP_COMMIT();

    float oacc[8][4];
#pragma unroll
    for (int nt = 0; nt < 8; nt++)
#pragma unroll
        for (int e = 0; e < 4; e++) oacc[nt][e] = 0.f;
    float m0 = -1e30f, m1 = -1e30f, l0 = 0.f, l1 = 0.f;

    for (int kt = 0; kt < nkt; kt++) {
        const int cur = kt & 1;
        CP_WAIT0();
        __syncthreads();
        if (kt + 1 < nkt) { load_kv(kt + 1, cur ^ 1); CP_COMMIT(); }

        float sacc[8][4];
#pragma unroll
        for (int nt = 0; nt < 8; nt++)
#pragma unroll
            for (int e = 0; e < 4; e++) sacc[nt][e] = 0.f;

        const uint32_t ksb = sb + KS0 + cur * 16384;
#pragma unroll
        for (int ch = 0; ch < 2; ch++)
#pragma unroll
            for (int ks = 0; ks < 4; ks++) {
                uint32_t af[4];
                ldsm4(af, sb + QS + ch * 8192 +
                          SWZ((wid * 16 + a_r) * 128 + (ks * 2 + a_c) * 16));
                uint32_t bf[4][4];
#pragma unroll
                for (int pt = 0; pt < 4; pt++) {
                    ldsm4(bf[pt], ksb + ch * 8192 +
                              SWZ((pt * 16 + b_r) * 128 + (ks * 2 + b_c) * 16));
                    cvt4(bf[pt]);
                }
#pragma unroll
                for (int nt = 0; nt < 8; nt++) {
                    const uint32_t* bb = bf[nt >> 1];
                    mma8(sacc[nt], af, (nt & 1) ? bb[2] : bb[0],
                         (nt & 1) ? bb[3] : bb[1]);
                }
            }

        if (kt == bx) {
            const int row0 = wid * 16 + gid;
#pragma unroll
            for (int nt = 0; nt < 8; nt++) {
                const int col = nt * 8 + tig * 2;
                if (col     > row0)     sacc[nt][0] = -1e30f;
                if (col + 1 > row0)     sacc[nt][1] = -1e30f;
                if (col     > row0 + 8) sacc[nt][2] = -1e30f;
                if (col + 1 > row0 + 8) sacc[nt][3] = -1e30f;
            }
        }

        float mx0 = -1e30f, mx1 = -1e30f;
#pragma unroll
        for (int nt = 0; nt < 8; nt++) {
            mx0 = fmaxf(mx0, fmaxf(sacc[nt][0], sacc[nt][1]));
            mx1 = fmaxf(mx1, fmaxf(sacc[nt][2], sacc[nt][3]));
        }
        mx0 = fmaxf(mx0, __shfl_xor_sync(0xffffffffu, mx0, 1));
        mx0 = fmaxf(mx0, __shfl_xor_sync(0xffffffffu, mx0, 2));
        mx1 = fmaxf(mx1, __shfl_xor_sync(0xffffffffu, mx1, 1));
        mx1 = fmaxf(mx1, __shfl_xor_sync(0xffffffffu, mx1, 2));
        const float mn0 = fmaxf(m0, mx0), mn1 = fmaxf(m1, mx1);
        const float c0 = __expf(m0 - mn0), c1 = __expf(m1 - mn1);
        m0 = mn0; m1 = mn1;
        float s0 = 0.f, s1 = 0.f;
#pragma unroll
        for (int nt = 0; nt < 8; nt++) {
            sacc[nt][0] = __expf(sacc[nt][0] - m0);
            sacc[nt][1] = __expf(sacc[nt][1] - m0);
            sacc[nt][2] = __expf(sacc[nt][2] - m1);
            sacc[nt][3] = __expf(sacc[nt][3] - m1);
            s0 += sacc[nt][0] + sacc[nt][1];
            s1 += sacc[nt][2] + sacc[nt][3];
        }
        s0 += __shfl_xor_sync(0xffffffffu, s0, 1);
        s0 += __shfl_xor_sync(0xffffffffu, s0, 2);
        s1 += __shfl_xor_sync(0xffffffffu, s1, 1);
        s1 += __shfl_xor_sync(0xffffffffu, s1, 2);
        l0 = l0 * c0 + s0;
        l1 = l1 * c1 + s1;
#pragma unroll
        for (int nt = 0; nt < 8; nt++) {
            oacc[nt][0] *= c0; oacc[nt][1] *= c0;
            oacc[nt][2] *= c1; oacc[nt][3] *= c1;
        }

#pragma unroll
        for (int nt = 0; nt < 8; nt++) {
            const int col = nt * 8 + tig * 2;
            const uint32_t cb = (col >> 5) * 2048;
            uint2 p0, p1;
            p0.x = f2tf32(sacc[nt][0]); p0.y = f2tf32(sacc[nt][1]);
            p1.x = f2tf32(sacc[nt][2]); p1.y = f2tf32(sacc[nt][3]);
            *(uint2*)(smem + PSo + cb + SWZ(gid * 128 + (col & 31) * 4)) = p0;
            *(uint2*)(smem + PSo + cb + SWZ((gid + 8) * 128 + (col & 31) * 4)) = p1;
        }
        __syncwarp();

        const uint32_t vsb = sb + VS0 + cur * 16384;
#pragma unroll
        for (int ch = 0; ch < 2; ch++)
#pragma unroll
            for (int ks = 0; ks < 4; ks++) {
                uint32_t af[4];
                ldsm4(af, sb + PSo + ch * 2048 +
                          SWZ(a_r * 128 + (ks * 2 + a_c) * 16));
                uint32_t bf[4][4];
#pragma unroll
                for (int pt = 0; pt < 4; pt++) {
                    ldsm4(bf[pt], vsb + ch * 8192 +
                              SWZ((pt * 16 + b_r) * 128 + (ks * 2 + b_c) * 16));
                    cvt4(bf[pt]);
                }
#pragma unroll
                for (int nt = 0; nt < 8; nt++) {
                    const uint32_t* bb = bf[nt >> 1];
                    mma8(oacc[nt], af, (nt & 1) ? bb[2] : bb[0],
                         (nt & 1) ? bb[3] : bb[1]);
                }
            }
        __syncthreads();
    }

    // write O tf32-rounded so proj GEMM can consume raw bits
    const float i0 = 1.0f / l0, i1 = 1.0f / l1;
    float* yp = g_y + ((size_t)b * TZ + q0 + wid * 16) * CZ + h * DD;
#pragma unroll
    for (int nt = 0; nt < 8; nt++) {
        const int d = nt * 8 + tig * 2;
        float2 v0 = {__uint_as_float(f2tf32(oacc[nt][0] * i0)),
                     __uint_as_float(f2tf32(oacc[nt][1] * i0))};
        float2 v1 = {__uint_as_float(f2tf32(oacc[nt][2] * i1)),
                     __uint_as_float(f2tf32(oacc[nt][3] * i1))};
        *(float2*)(yp + (size_t)gid * CZ + d) = v0;
        *(float2*)(yp + (size_t)(gid + 8) * CZ + d) = v1;
    }
}

// ---------------------------------------------------------------------------
extern "C" void kernel_launch(void* const* d_in, const int* in_sizes, int n_in,
                              void* d_out, int out_size)
{
    const float* x      = (const float*)d_in[0];
    const float* w_attn = (const float*)d_in[1];
    const float* b_attn = (const float*)d_in[2];
    const float* w_proj = (const float*)d_in[3];
    const float* b_proj = (const float*)d_in[4];
    float* out = (float*)d_out;

    void *y_ptr, *xa_ptr, *wa_ptr, *wp_ptr;
    cudaGetSymbolAddress(&y_ptr, g_y);
    cudaGetSymbolAddress(&xa_ptr, g_xa);
    cudaGetSymbolAddress(&wa_ptr, g_wa);
    cudaGetSymbolAddress(&wp_ptr, g_wp);

    cudaFuncSetAttribute(mma_gemm<1>, cudaFuncAttributeMaxDynamicSharedMemorySize, GEMM_SMEM);
    cudaFuncSetAttribute(mma_gemm<0>, cudaFuncAttributeMaxDynamicSharedMemorySize, GEMM_SMEM);
    cudaFuncSetAttribute(attn_mma, cudaFuncAttributeMaxDynamicSharedMemorySize, ATT_SMEM);

    // 0) pre-convert inputs to tf32 (+ transpose weights to [N][K])
    cvt_x<<<M_TOT * KD / 4 / 256, 256>>>((const float4*)x, (uint4*)xa_ptr);
    wtrans<<<dim3(N_QKV / 32, KD / 32), 256>>>(w_attn, (uint32_t*)wa_ptr, N_QKV);
    wtrans<<<dim3(CZ / 32, KD / 32), 256>>>(w_proj, (uint32_t*)wp_ptr, CZ);

    // 1) QKV GEMM -> q/k [B,H,T,D], v [B,H,D,T]
    mma_gemm<1><<<dim3(N_QKV / 128, M_TOT / 128), 256, GEMM_SMEM>>>(
        (const uint32_t*)xa_ptr, (const uint32_t*)wa_ptr, b_attn, nullptr, N_QKV);

    // 2) Flash attention (tf32 mma) -> g_y [B,T,C] (tf32-valued)
    attn_mma<<<dim3(TZ / 64, HH, BZ), 128, ATT_SMEM>>>();

    // 3) Proj GEMM -> d_out
    mma_gemm<0><<<dim3(CZ / 128, M_TOT / 128), 256, GEMM_SMEM>>>(
        (const uint32_t*)y_ptr, (const uint32_t*)wp_ptr, b_proj, out, CZ);
}

// round 6
// speedup vs baseline: 9.9320x; 1.9454x over previous
#include <cuda_runtime.h>
#include <cuda_fp16.h>
#include <cstdint>
#include <math.h>

#define BZ 2
#define TZ 2048
#define CZ 1024
#define HH 16
#define DD 64
#define M_TOT (BZ * TZ)      // 4096
#define N_QKV (3 * CZ)       // 3072
#define KD CZ                // 1024
#define BKH 64               // K halves per GEMM stage (64 h = 128B row)
#define NSTG (KD / BKH)      // 16 stages

// Scratch (allocation-free rule: __device__ globals)
__device__ __half g_qh[BZ * HH * TZ * DD];   // [B,H,T,D], pre-scaled by 1/8
__device__ __half g_kh[BZ * HH * TZ * DD];   // [B,H,T,D]
__device__ __half g_vh[BZ * HH * TZ * DD];   // [B,H,D,T] (TRANSPOSED)
__device__ __half g_yh[BZ * TZ * CZ];        // attention out, fp16
__device__ __half g_xh[M_TOT * KD];          // x   fp16 [M][K]
__device__ __half g_wah[N_QKV * KD];         // w_attn^T fp16 [N][K]
__device__ __half g_wph[CZ * KD];            // w_proj^T fp16 [N][K]

// ---------------------------------------------------------------------------
// Portable PTX helpers
// ---------------------------------------------------------------------------
__device__ __forceinline__ uint32_t smem_u32(const void* p) {
    uint32_t a;
    asm("{ .reg .u64 t; cvta.to.shared.u64 t, %1; cvt.u32.u64 %0, t; }"
        : "=r"(a) : "l"(p));
    return a;
}
#define SWZ(x) ((uint32_t)(x) ^ ((((uint32_t)(x)) >> 3) & 0x70))

__device__ __forceinline__ void ldsm4(uint32_t* r, uint32_t addr) {
    asm volatile("ldmatrix.sync.aligned.m8n8.x4.shared.b16 {%0,%1,%2,%3}, [%4];"
                 : "=r"(r[0]), "=r"(r[1]), "=r"(r[2]), "=r"(r[3]) : "r"(addr));
}
// fp16 MMA, fp32 accumulate
__device__ __forceinline__ void mma16(float* c, const uint32_t* a,
                                      uint32_t b0, uint32_t b1) {
    asm volatile(
        "mma.sync.aligned.m16n8k16.row.col.f32.f16.f16.f32 "
        "{%0,%1,%2,%3}, {%4,%5,%6,%7}, {%8,%9}, {%0,%1,%2,%3};"
        : "+f"(c[0]), "+f"(c[1]), "+f"(c[2]), "+f"(c[3])
        : "r"(a[0]), "r"(a[1]), "r"(a[2]), "r"(a[3]), "r"(b0), "r"(b1));
}
__device__ __forceinline__ void cpasync16(uint32_t dst, const void* src) {
    asm volatile("cp.async.cg.shared.global [%0], [%1], 16;"
                 :: "r"(dst), "l"(src));
}
#define CP_COMMIT() asm volatile("cp.async.commit_group;")
#define CP_WAITG(n) asm volatile("cp.async.wait_group %0;" :: "n"(n))
#define CP_WAIT0()  asm volatile("cp.async.wait_group 0;")

__device__ __forceinline__ uint32_t pack2(float a, float b) {
    __half2 h = __floats2half2_rn(a, b);
    return *(uint32_t*)&h;
}

// ===========================================================================
// Pre-pass kernels
// ===========================================================================
__global__ void __launch_bounds__(256) cvt_x(const float4* __restrict__ X,
                                             uint2* __restrict__ Xt) {
    const int i = blockIdx.x * 256 + threadIdx.x;
    float4 v = X[i];
    uint2 t;
    t.x = pack2(v.x, v.y);
    t.y = pack2(v.z, v.w);
    Xt[i] = t;
}

// W [K=1024][N] -> Wt [N][K=1024] fp16
__global__ void __launch_bounds__(256) wtrans(const float* __restrict__ W,
                                              __half* __restrict__ Wt, int N) {
    __shared__ float t[32][33];
    const int tx = threadIdx.x & 31, ty = threadIdx.x >> 5;
    const int n0 = blockIdx.x * 32, k0 = blockIdx.y * 32;
#pragma unroll
    for (int i = 0; i < 4; i++)
        t[ty + i * 8][tx] = W[(size_t)(k0 + ty + i * 8) * N + n0 + tx];
    __syncthreads();
#pragma unroll
    for (int i = 0; i < 4; i++)
        Wt[(size_t)(n0 + ty + i * 8) * KD + k0 + tx] =
            __float2half_rn(t[tx][ty + i * 8]);
}

// ===========================================================================
// fp16 GEMM, 3-buffer cp.async pipeline.
// A fp16 [M][K], Bt fp16 [N][K]. C = A*Bt^T + bias.
// 128x128 tile, 64 halves/stage, 256 threads, warp grid 2x4 (64x32/warp).
// EPI=1: scatter to g_qh/g_kh/g_vh; EPI=0: fp32 row-major store.
// ===========================================================================
#define GEMM_SMEM 98304   // 3 stages x (16KB A + 16KB B)

template <int EPI>
__global__ void __launch_bounds__(256) mma_gemm(
    const __half* __restrict__ A, const __half* __restrict__ Bt,
    const float* __restrict__ bias, float* __restrict__ Cout, int N)
{
    extern __shared__ char smem[];
    const uint32_t sbase = smem_u32(smem);
    const int tid = threadIdx.x;
    const int lane = tid & 31;
    const int wid = tid >> 5;
    const int bm = blockIdx.y * 128;
    const int bn = blockIdx.x * 128;
    const int wm = (wid >> 2) * 64;
    const int wn = (wid & 3) * 32;

    const int a_r = lane & 15;
    const int a_c = lane >> 4;
    const int b_r = ((lane >> 4) & 1) * 8 + (lane & 7);
    const int b_c = (lane >> 3) & 1;

    float acc[4][4][4];
#pragma unroll
    for (int i = 0; i < 4; i++)
#pragma unroll
        for (int j = 0; j < 4; j++)
#pragma unroll
            for (int e = 0; e < 4; e++) acc[i][j][e] = 0.f;

    auto issue_stage = [&](int kt, int buf) {
#pragma unroll
        for (int i = 0; i < 4; i++) {
            const int idx = i * 256 + tid;
            const int r = idx >> 3, c = idx & 7;
            const uint32_t so = SWZ(r * 128 + c * 16);
            cpasync16(sbase + buf * 32768 + so,
                      A + (size_t)(bm + r) * KD + kt * BKH + c * 8);
            cpasync16(sbase + buf * 32768 + 16384 + so,
                      Bt + (size_t)(bn + r) * KD + kt * BKH + c * 8);
        }
    };

    auto compute = [&](int buf) {
        const uint32_t abase = sbase + buf * 32768;
        const uint32_t bbase = abase + 16384;
#pragma unroll
        for (int g = 0; g < 4; g++) {       // 4 x k16
            uint32_t af[4][4];
#pragma unroll
            for (int mt = 0; mt < 4; mt++)
                ldsm4(af[mt],
                      abase + SWZ((wm + mt * 16 + a_r) * 128 + (g * 2 + a_c) * 16));
            uint32_t bf[2][4];
#pragma unroll
            for (int pt = 0; pt < 2; pt++)
                ldsm4(bf[pt],
                      bbase + SWZ((wn + pt * 16 + b_r) * 128 + (g * 2 + b_c) * 16));
#pragma unroll
            for (int mt = 0; mt < 4; mt++)
#pragma unroll
                for (int nt = 0; nt < 4; nt++) {
                    const uint32_t* bb = bf[nt >> 1];
                    const uint32_t b0 = (nt & 1) ? bb[2] : bb[0];
                    const uint32_t b1 = (nt & 1) ? bb[3] : bb[1];
                    mma16(acc[mt][nt], af[mt], b0, b1);
                }
        }
    };

    issue_stage(0, 0); CP_COMMIT();
    issue_stage(1, 1); CP_COMMIT();

    for (int kt = 0; kt < NSTG; kt++) {
        CP_WAITG(1);            // stage kt resident
        __syncthreads();        // guards buffer reuse
        if (kt + 2 < NSTG) issue_stage(kt + 2, (kt + 2) % 3);
        CP_COMMIT();            // empty group in tail keeps invariant
        compute(kt % 3);
    }

    const int gid = lane >> 2, tig = lane & 3;
#pragma unroll
    for (int nt = 0; nt < 4; nt++) {
        const int col = bn + wn + nt * 8 + tig * 2;
        const float bi0 = bias[col], bi1 = bias[col + 1];
#pragma unroll
        for (int mt = 0; mt < 4; mt++) {
            const int r0 = bm + wm + mt * 16 + gid;
            const int r1 = r0 + 8;
            const float v00 = acc[mt][nt][0] + bi0, v01 = acc[mt][nt][1] + bi1;
            const float v10 = acc[mt][nt][2] + bi0, v11 = acc[mt][nt][3] + bi1;
            if (EPI == 1) {
                const int sel = col >> 10;
                const int cc = col & 1023;
                const int h = cc >> 6, d = cc & 63;
                const int b0i = r0 >> 11, t0 = r0 & (TZ - 1);
                const int b1i = r1 >> 11, t1 = r1 & (TZ - 1);
                if (sel == 2) {  // V transposed [B,H,D,T]
                    const size_t p0 = ((size_t)(b0i * HH + h) * DD + d) * TZ + t0;
                    const size_t p1 = ((size_t)(b1i * HH + h) * DD + d) * TZ + t1;
                    g_vh[p0] = __float2half_rn(v00);
                    g_vh[p0 + TZ] = __float2half_rn(v01);
                    g_vh[p1] = __float2half_rn(v10);
                    g_vh[p1 + TZ] = __float2half_rn(v11);
                } else if (sel == 0) {  // Q pre-scaled by 1/sqrt(D)
                    const size_t p0 = (((size_t)(b0i * HH + h)) * TZ + t0) * DD + d;
                    const size_t p1 = (((size_t)(b1i * HH + h)) * TZ + t1) * DD + d;
                    *(uint32_t*)&g_qh[p0] = pack2(v00 * 0.125f, v01 * 0.125f);
                    *(uint32_t*)&g_qh[p1] = pack2(v10 * 0.125f, v11 * 0.125f);
                } else {
                    const size_t p0 = (((size_t)(b0i * HH + h)) * TZ + t0) * DD + d;
                    const size_t p1 = (((size_t)(b1i * HH + h)) * TZ + t1) * DD + d;
                    *(uint32_t*)&g_kh[p0] = pack2(v00, v01);
                    *(uint32_t*)&g_kh[p1] = pack2(v10, v11);
                }
            } else {
                *(float2*)&Cout[(size_t)r0 * N + col] = make_float2(v00, v01);
                *(float2*)&Cout[(size_t)r1 * N + col] = make_float2(v10, v11);
            }
        }
    }
}

// ===========================================================================
// fp16 flash attention. 64 q/block (4 warps x 16 rows), K-tiles of 64.
// SMEM (48KB): Q @0 (8KB); K 2x8KB @8192; V 2x8KB @24576; P/warp 2KB @40960.
// All tiles: 64 rows x 64 halves (128B rows, SW128).
// ===========================================================================
#define ATT_SMEM 49152

__global__ void __launch_bounds__(128) attn_mma()
{
    extern __shared__ char smem[];
    const uint32_t sb = smem_u32(smem);
    const int tid = threadIdx.x, lane = tid & 31, wid = tid >> 5;
    const int bx = blockIdx.x;
    const int h = blockIdx.y, b = blockIdx.z;
    const int q0 = bx * 64;
    const size_t bh = (size_t)(b * HH + h);
    const __half* qg = g_qh + bh * TZ * DD;
    const __half* kg = g_kh + bh * TZ * DD;
    const __half* vg = g_vh + bh * DD * TZ;   // [d][t]

    const uint32_t QS = 0, KS0 = 8192, VS0 = 24576;
    const uint32_t PSo = 40960 + wid * 2048;

    const int a_r = lane & 15;
    const int a_c = lane >> 4;
    const int b_r = ((lane >> 4) & 1) * 8 + (lane & 7);
    const int b_c = (lane >> 3) & 1;
    const int gid = lane >> 2, tig = lane & 3;

    // Q tile (already scaled): 64 rows x 8 chunks, 4 per thread
    {
        const __half* qp = qg + (size_t)q0 * DD;
#pragma unroll
        for (int i = 0; i < 4; i++) {
            const int idx = i * 128 + tid;
            const int row = idx >> 3, c = idx & 7;
            cpasync16(sb + QS + SWZ(row * 128 + c * 16), qp + row * DD + c * 8);
        }
    }

    auto load_kv = [&](int kt, int buf) {
        const __half* kp = kg + (size_t)(kt * 64) * DD;
#pragma unroll
        for (int i = 0; i < 4; i++) {
            const int idx = i * 128 + tid;
            const int key = idx >> 3, c = idx & 7;
            cpasync16(sb + KS0 + buf * 8192 + SWZ(key * 128 + c * 16),
                      kp + key * DD + c * 8);
        }
        const __half* vp = vg + kt * 64;
#pragma unroll
        for (int i = 0; i < 4; i++) {
            const int idx = i * 128 + tid;
            const int d = idx >> 3, c = idx & 7;
            cpasync16(sb + VS0 + buf * 8192 + SWZ(d * 128 + c * 16),
                      vp + (size_t)d * TZ + c * 8);
        }
    };

    const int nkt = bx + 1;
    load_kv(0, 0);
    CP_COMMIT();

    float oacc[8][4];
#pragma unroll
    for (int nt = 0; nt < 8; nt++)
#pragma unroll
        for (int e = 0; e < 4; e++) oacc[nt][e] = 0.f;
    float m0 = -1e30f, m1 = -1e30f, l0 = 0.f, l1 = 0.f;

    for (int kt = 0; kt < nkt; kt++) {
        const int cur = kt & 1;
        CP_WAIT0();
        __syncthreads();
        if (kt + 1 < nkt) { load_kv(kt + 1, cur ^ 1); CP_COMMIT(); }

        // ---- S = Q K^T ----
        float sacc[8][4];
#pragma unroll
        for (int nt = 0; nt < 8; nt++)
#pragma unroll
            for (int e = 0; e < 4; e++) sacc[nt][e] = 0.f;

        const uint32_t ksb = sb + KS0 + cur * 8192;
#pragma unroll
        for (int g = 0; g < 4; g++) {
            uint32_t af[4];
            ldsm4(af, sb + QS + SWZ((wid * 16 + a_r) * 128 + (g * 2 + a_c) * 16));
            uint32_t bf[4][4];
#pragma unroll
            for (int pt = 0; pt < 4; pt++)
                ldsm4(bf[pt], ksb + SWZ((pt * 16 + b_r) * 128 + (g * 2 + b_c) * 16));
#pragma unroll
            for (int nt = 0; nt < 8; nt++) {
                const uint32_t* bb = bf[nt >> 1];
                mma16(sacc[nt], af, (nt & 1) ? bb[2] : bb[0],
                      (nt & 1) ? bb[3] : bb[1]);
            }
        }

        // ---- causal mask on diagonal tile ----
        if (kt == bx) {
            const int row0 = wid * 16 + gid;
#pragma unroll
            for (int nt = 0; nt < 8; nt++) {
                const int col = nt * 8 + tig * 2;
                if (col     > row0)     sacc[nt][0] = -1e30f;
                if (col + 1 > row0)     sacc[nt][1] = -1e30f;
                if (col     > row0 + 8) sacc[nt][2] = -1e30f;
                if (col + 1 > row0 + 8) sacc[nt][3] = -1e30f;
            }
        }

        // ---- online softmax ----
        float mx0 = -1e30f, mx1 = -1e30f;
#pragma unroll
        for (int nt = 0; nt < 8; nt++) {
            mx0 = fmaxf(mx0, fmaxf(sacc[nt][0], sacc[nt][1]));
            mx1 = fmaxf(mx1, fmaxf(sacc[nt][2], sacc[nt][3]));
        }
        mx0 = fmaxf(mx0, __shfl_xor_sync(0xffffffffu, mx0, 1));
        mx0 = fmaxf(mx0, __shfl_xor_sync(0xffffffffu, mx0, 2));
        mx1 = fmaxf(mx1, __shfl_xor_sync(0xffffffffu, mx1, 1));
        mx1 = fmaxf(mx1, __shfl_xor_sync(0xffffffffu, mx1, 2));
        const float mn0 = fmaxf(m0, mx0), mn1 = fmaxf(m1, mx1);
        const float c0 = __expf(m0 - mn0), c1 = __expf(m1 - mn1);
        m0 = mn0; m1 = mn1;
        float s0 = 0.f, s1 = 0.f;
#pragma unroll
        for (int nt = 0; nt < 8; nt++) {
            sacc[nt][0] = __expf(sacc[nt][0] - m0);
            sacc[nt][1] = __expf(sacc[nt][1] - m0);
            sacc[nt][2] = __expf(sacc[nt][2] - m1);
            sacc[nt][3] = __expf(sacc[nt][3] - m1);
            s0 += sacc[nt][0] + sacc[nt][1];
            s1 += sacc[nt][2] + sacc[nt][3];
        }
        s0 += __shfl_xor_sync(0xffffffffu, s0, 1);
        s0 += __shfl_xor_sync(0xffffffffu, s0, 2);
        s1 += __shfl_xor_sync(0xffffffffu, s1, 1);
        s1 += __shfl_xor_sync(0xffffffffu, s1, 2);
        l0 = l0 * c0 + s0;
        l1 = l1 * c1 + s1;
#pragma unroll
        for (int nt = 0; nt < 8; nt++) {
            oacc[nt][0] *= c0; oacc[nt][1] *= c0;
            oacc[nt][2] *= c1; oacc[nt][3] *= c1;
        }

        // ---- stage P (fp16) per-warp as A-operand [16 rows][64 keys] ----
#pragma unroll
        for (int nt = 0; nt < 8; nt++) {
            const int col = nt * 8 + tig * 2;
            *(uint32_t*)(smem + PSo + SWZ(gid * 128 + col * 2)) =
                pack2(sacc[nt][0], sacc[nt][1]);
            *(uint32_t*)(smem + PSo + SWZ((gid + 8) * 128 + col * 2)) =
                pack2(sacc[nt][2], sacc[nt][3]);
        }
        __syncwarp();

        // ---- O += P V ----
        const uint32_t vsb = sb + VS0 + cur * 8192;
#pragma unroll
        for (int g = 0; g < 4; g++) {
            uint32_t af[4];
            ldsm4(af, sb + PSo + SWZ(a_r * 128 + (g * 2 + a_c) * 16));
            uint32_t bf[4][4];
#pragma unroll
            for (int pt = 0; pt < 4; pt++)
                ldsm4(bf[pt], vsb + SWZ((pt * 16 + b_r) * 128 + (g * 2 + b_c) * 16));
#pragma unroll
            for (int nt = 0; nt < 8; nt++) {
                const uint32_t* bb = bf[nt >> 1];
                mma16(oacc[nt], af, (nt & 1) ? bb[2] : bb[0],
                      (nt & 1) ? bb[3] : bb[1]);
            }
        }
        __syncthreads();
    }

    // ---- write O (fp16) to g_yh [B,T,C] ----
    const float i0 = 1.0f / l0, i1 = 1.0f / l1;
    __half* yp = g_yh + ((size_t)b * TZ + q0 + wid * 16) * CZ + h * DD;
#pragma unroll
    for (int nt = 0; nt < 8; nt++) {
        const int d = nt * 8 + tig * 2;
        *(uint32_t*)(yp + (size_t)gid * CZ + d) =
            pack2(oacc[nt][0] * i0, oacc[nt][1] * i0);
        *(uint32_t*)(yp + (size_t)(gid + 8) * CZ + d) =
            pack2(oacc[nt][2] * i1, oacc[nt][3] * i1);
    }
}

// ---------------------------------------------------------------------------
extern "C" void kernel_launch(void* const* d_in, const int* in_sizes, int n_in,
                              void* d_out, int out_size)
{
    const float* x      = (const float*)d_in[0];
    const float* w_attn = (const float*)d_in[1];
    const float* b_attn = (const float*)d_in[2];
    const float* w_proj = (const float*)d_in[3];
    const float* b_proj = (const float*)d_in[4];
    float* out = (float*)d_out;

    void *y_ptr, *xa_ptr, *wa_ptr, *wp_ptr;
    cudaGetSymbolAddress(&y_ptr, g_yh);
    cudaGetSymbolAddress(&xa_ptr, g_xh);
    cudaGetSymbolAddress(&wa_ptr, g_wah);
    cudaGetSymbolAddress(&wp_ptr, g_wph);

    cudaFuncSetAttribute(mma_gemm<1>, cudaFuncAttributeMaxDynamicSharedMemorySize, GEMM_SMEM);
    cudaFuncSetAttribute(mma_gemm<0>, cudaFuncAttributeMaxDynamicSharedMemorySize, GEMM_SMEM);
    cudaFuncSetAttribute(attn_mma, cudaFuncAttributeMaxDynamicSharedMemorySize, ATT_SMEM);

    // 0) pre-convert inputs to fp16 (+ transpose weights to [N][K])
    cvt_x<<<M_TOT * KD / 4 / 256, 256>>>((const float4*)x, (uint2*)xa_ptr);
    wtrans<<<dim3(N_QKV / 32, KD / 32), 256>>>(w_attn, (__half*)wa_ptr, N_QKV);
    wtrans<<<dim3(CZ / 32, KD / 32), 256>>>(w_proj, (__half*)wp_ptr, CZ);

    // 1) QKV GEMM -> q(scaled)/k [B,H,T,D], v [B,H,D,T], all fp16
    mma_gemm<1><<<dim3(N_QKV / 128, M_TOT / 128), 256, GEMM_SMEM>>>(
        (const __half*)xa_ptr, (const __half*)wa_ptr, b_attn, nullptr, N_QKV);

    // 2) Flash attention (fp16 mma) -> g_yh [B,T,C]
    attn_mma<<<dim3(TZ / 64, HH, BZ), 128, ATT_SMEM>>>();

    // 3) Proj GEMM -> d_out (fp32)
    mma_gemm<0><<<dim3(CZ / 128, M_TOT / 128), 256, GEMM_SMEM>>>(
        (const __half*)y_ptr, (const __half*)wp_ptr, b_proj, out, CZ);
}

// round 7
// speedup vs baseline: 9.9502x; 1.0018x over previous
#include <cuda_runtime.h>
#include <cuda_fp16.h>
#include <cstdint>
#include <math.h>

#define BZ 2
#define TZ 2048
#define CZ 1024
#define HH 16
#define DD 64
#define M_TOT (BZ * TZ)      // 4096
#define N_QKV (3 * CZ)       // 3072
#define KD CZ                // 1024
#define BKH 64               // K halves per GEMM stage (64 h = 128B row)
#define NSTG (KD / BKH)      // 16 stages

// Q pre-scale: 1/sqrt(64) * log2(e)  (softmax done in base-2)
#define QSCALE 0.18033688011112042f

// Scratch (allocation-free rule: __device__ globals)
__device__ __half g_qh[BZ * HH * TZ * DD];   // [B,H,T,D], pre-scaled
__device__ __half g_kh[BZ * HH * TZ * DD];   // [B,H,T,D]
__device__ __half g_vh[BZ * HH * TZ * DD];   // [B,H,D,T] (TRANSPOSED)
__device__ __half g_yh[BZ * TZ * CZ];        // attention out, fp16
__device__ __half g_xh[M_TOT * KD];          // x   fp16 [M][K]
__device__ __half g_wah[N_QKV * KD];         // w_attn^T fp16 [N][K]
__device__ __half g_wph[CZ * KD];            // w_proj^T fp16 [N][K]

// ---------------------------------------------------------------------------
// Portable PTX helpers
// ---------------------------------------------------------------------------
__device__ __forceinline__ uint32_t smem_u32(const void* p) {
    uint32_t a;
    asm("{ .reg .u64 t; cvta.to.shared.u64 t, %1; cvt.u32.u64 %0, t; }"
        : "=r"(a) : "l"(p));
    return a;
}
#define SWZ(x) ((uint32_t)(x) ^ ((((uint32_t)(x)) >> 3) & 0x70))

__device__ __forceinline__ void ldsm4(uint32_t* r, uint32_t addr) {
    asm volatile("ldmatrix.sync.aligned.m8n8.x4.shared.b16 {%0,%1,%2,%3}, [%4];"
                 : "=r"(r[0]), "=r"(r[1]), "=r"(r[2]), "=r"(r[3]) : "r"(addr));
}
__device__ __forceinline__ void mma16(float* c, const uint32_t* a,
                                      uint32_t b0, uint32_t b1) {
    asm volatile(
        "mma.sync.aligned.m16n8k16.row.col.f32.f16.f16.f32 "
        "{%0,%1,%2,%3}, {%4,%5,%6,%7}, {%8,%9}, {%0,%1,%2,%3};"
        : "+f"(c[0]), "+f"(c[1]), "+f"(c[2]), "+f"(c[3])
        : "r"(a[0]), "r"(a[1]), "r"(a[2]), "r"(a[3]), "r"(b0), "r"(b1));
}
__device__ __forceinline__ void cpasync16(uint32_t dst, const void* src) {
    asm volatile("cp.async.cg.shared.global [%0], [%1], 16;"
                 :: "r"(dst), "l"(src));
}
#define CP_COMMIT() asm volatile("cp.async.commit_group;")
#define CP_WAITG(n) asm volatile("cp.async.wait_group %0;" :: "n"(n))
#define CP_WAIT0()  asm volatile("cp.async.wait_group 0;")

__device__ __forceinline__ uint32_t pack2(float a, float b) {
    __half2 h = __floats2half2_rn(a, b);
    return *(uint32_t*)&h;
}
__device__ __forceinline__ float ex2(float x) {
    float r;
    asm("ex2.approx.f32 %0, %1;" : "=f"(r) : "f"(x));
    return r;
}

// ===========================================================================
// Pre-pass kernels
// ===========================================================================
__global__ void __launch_bounds__(256) cvt_x(const float4* __restrict__ X,
                                             uint2* __restrict__ Xt) {
    const int i = blockIdx.x * 256 + threadIdx.x;
    float4 v = X[i];
    uint2 t;
    t.x = pack2(v.x, v.y);
    t.y = pack2(v.z, v.w);
    Xt[i] = t;
}

// W [K=1024][N] -> Wt [N][K=1024] fp16
__global__ void __launch_bounds__(256) wtrans(const float* __restrict__ W,
                                              __half* __restrict__ Wt, int N) {
    __shared__ float t[32][33];
    const int tx = threadIdx.x & 31, ty = threadIdx.x >> 5;
    const int n0 = blockIdx.x * 32, k0 = blockIdx.y * 32;
#pragma unroll
    for (int i = 0; i < 4; i++)
        t[ty + i * 8][tx] = W[(size_t)(k0 + ty + i * 8) * N + n0 + tx];
    __syncthreads();
#pragma unroll
    for (int i = 0; i < 4; i++)
        Wt[(size_t)(n0 + ty + i * 8) * KD + k0 + tx] =
            __float2half_rn(t[tx][ty + i * 8]);
}

// ===========================================================================
// fp16 GEMM (validated R6): 3-buffer cp.async pipeline, 128x128 tile.
// ===========================================================================
#define GEMM_SMEM 98304   // 3 stages x (16KB A + 16KB B)

template <int EPI>
__global__ void __launch_bounds__(256) mma_gemm(
    const __half* __restrict__ A, const __half* __restrict__ Bt,
    const float* __restrict__ bias, float* __restrict__ Cout, int N)
{
    extern __shared__ char smem[];
    const uint32_t sbase = smem_u32(smem);
    const int tid = threadIdx.x;
    const int lane = tid & 31;
    const int wid = tid >> 5;
    const int bm = blockIdx.y * 128;
    const int bn = blockIdx.x * 128;
    const int wm = (wid >> 2) * 64;
    const int wn = (wid & 3) * 32;

    const int a_r = lane & 15;
    const int a_c = lane >> 4;
    const int b_r = ((lane >> 4) & 1) * 8 + (lane & 7);
    const int b_c = (lane >> 3) & 1;

    float acc[4][4][4];
#pragma unroll
    for (int i = 0; i < 4; i++)
#pragma unroll
        for (int j = 0; j < 4; j++)
#pragma unroll
            for (int e = 0; e < 4; e++) acc[i][j][e] = 0.f;

    auto issue_stage = [&](int kt, int buf) {
#pragma unroll
        for (int i = 0; i < 4; i++) {
            const int idx = i * 256 + tid;
            const int r = idx >> 3, c = idx & 7;
            const uint32_t so = SWZ(r * 128 + c * 16);
            cpasync16(sbase + buf * 32768 + so,
                      A + (size_t)(bm + r) * KD + kt * BKH + c * 8);
            cpasync16(sbase + buf * 32768 + 16384 + so,
                      Bt + (size_t)(bn + r) * KD + kt * BKH + c * 8);
        }
    };

    auto compute = [&](int buf) {
        const uint32_t abase = sbase + buf * 32768;
        const uint32_t bbase = abase + 16384;
#pragma unroll
        for (int g = 0; g < 4; g++) {
            uint32_t af[4][4];
#pragma unroll
            for (int mt = 0; mt < 4; mt++)
                ldsm4(af[mt],
                      abase + SWZ((wm + mt * 16 + a_r) * 128 + (g * 2 + a_c) * 16));
            uint32_t bf[2][4];
#pragma unroll
            for (int pt = 0; pt < 2; pt++)
                ldsm4(bf[pt],
                      bbase + SWZ((wn + pt * 16 + b_r) * 128 + (g * 2 + b_c) * 16));
#pragma unroll
            for (int mt = 0; mt < 4; mt++)
#pragma unroll
                for (int nt = 0; nt < 4; nt++) {
                    const uint32_t* bb = bf[nt >> 1];
                    const uint32_t b0 = (nt & 1) ? bb[2] : bb[0];
                    const uint32_t b1 = (nt & 1) ? bb[3] : bb[1];
                    mma16(acc[mt][nt], af[mt], b0, b1);
                }
        }
    };

    issue_stage(0, 0); CP_COMMIT();
    issue_stage(1, 1); CP_COMMIT();

    for (int kt = 0; kt < NSTG; kt++) {
        CP_WAITG(1);
        __syncthreads();
        if (kt + 2 < NSTG) issue_stage(kt + 2, (kt + 2) % 3);
        CP_COMMIT();
        compute(kt % 3);
    }

    const int gid = lane >> 2, tig = lane & 3;
#pragma unroll
    for (int nt = 0; nt < 4; nt++) {
        const int col = bn + wn + nt * 8 + tig * 2;
        const float bi0 = bias[col], bi1 = bias[col + 1];
#pragma unroll
        for (int mt = 0; mt < 4; mt++) {
            const int r0 = bm + wm + mt * 16 + gid;
            const int r1 = r0 + 8;
            const float v00 = acc[mt][nt][0] + bi0, v01 = acc[mt][nt][1] + bi1;
            const float v10 = acc[mt][nt][2] + bi0, v11 = acc[mt][nt][3] + bi1;
            if (EPI == 1) {
                const int sel = col >> 10;
                const int cc = col & 1023;
                const int h = cc >> 6, d = cc & 63;
                const int b0i = r0 >> 11, t0 = r0 & (TZ - 1);
                const int b1i = r1 >> 11, t1 = r1 & (TZ - 1);
                if (sel == 2) {  // V transposed [B,H,D,T]
                    const size_t p0 = ((size_t)(b0i * HH + h) * DD + d) * TZ + t0;
                    const size_t p1 = ((size_t)(b1i * HH + h) * DD + d) * TZ + t1;
                    g_vh[p0] = __float2half_rn(v00);
                    g_vh[p0 + TZ] = __float2half_rn(v01);
                    g_vh[p1] = __float2half_rn(v10);
                    g_vh[p1 + TZ] = __float2half_rn(v11);
                } else if (sel == 0) {  // Q pre-scaled (incl. log2e)
                    const size_t p0 = (((size_t)(b0i * HH + h)) * TZ + t0) * DD + d;
                    const size_t p1 = (((size_t)(b1i * HH + h)) * TZ + t1) * DD + d;
                    *(uint32_t*)&g_qh[p0] = pack2(v00 * QSCALE, v01 * QSCALE);
                    *(uint32_t*)&g_qh[p1] = pack2(v10 * QSCALE, v11 * QSCALE);
                } else {
                    const size_t p0 = (((size_t)(b0i * HH + h)) * TZ + t0) * DD + d;
                    const size_t p1 = (((size_t)(b1i * HH + h)) * TZ + t1) * DD + d;
                    *(uint32_t*)&g_kh[p0] = pack2(v00, v01);
                    *(uint32_t*)&g_kh[p1] = pack2(v10, v11);
                }
            } else {
                *(float2*)&Cout[(size_t)r0 * N + col] = make_float2(v00, v01);
                *(float2*)&Cout[(size_t)r1 * N + col] = make_float2(v10, v11);
            }
        }
    }
}

// ===========================================================================
// fp16 flash attention v2: 128 q/block, 8 warps x 16 rows, K-tiles of 64.
// P stays in registers (C-frag == A-frag layout). Q frags hoisted.
// Softmax in base-2 (log2e folded into Q). Above-diagonal warps skip tiles.
// SMEM (48KB): Q @0 (16KB); K 2x8KB @16384; V 2x8KB @32768.
// ===========================================================================
#define ATT_SMEM 49152

__global__ void __launch_bounds__(256) attn_mma()
{
    extern __shared__ char smem[];
    const uint32_t sb = smem_u32(smem);
    const int tid = threadIdx.x, lane = tid & 31, wid = tid >> 5;
    const int bx = blockIdx.x;
    const int h = blockIdx.y, b = blockIdx.z;
    const int q0 = bx * 128;
    const size_t bh = (size_t)(b * HH + h);
    const __half* qg = g_qh + bh * TZ * DD;
    const __half* kg = g_kh + bh * TZ * DD;
    const __half* vg = g_vh + bh * DD * TZ;   // [d][t]

    const uint32_t QS = 0, KS0 = 16384, VS0 = 32768;

    const int a_r = lane & 15;
    const int a_c = lane >> 4;
    const int b_r = ((lane >> 4) & 1) * 8 + (lane & 7);
    const int b_c = (lane >> 3) & 1;
    const int gid = lane >> 2, tig = lane & 3;
    const int wrow0 = q0 + wid * 16;          // warp's first global q row

    // Q tile: 128 rows x 8 chunks = 1024 cp.async, 4 per thread
    {
        const __half* qp = qg + (size_t)q0 * DD;
#pragma unroll
        for (int i = 0; i < 4; i++) {
            const int idx = i * 256 + tid;
            const int row = idx >> 3, c = idx & 7;
            cpasync16(sb + QS + SWZ(row * 128 + c * 16), qp + row * DD + c * 8);
        }
    }

    auto load_kv = [&](int kt, int buf) {
        const __half* kp = kg + (size_t)(kt * 64) * DD;
#pragma unroll
        for (int i = 0; i < 2; i++) {
            const int idx = i * 256 + tid;
            const int key = idx >> 3, c = idx & 7;
            cpasync16(sb + KS0 + buf * 8192 + SWZ(key * 128 + c * 16),
                      kp + key * DD + c * 8);
        }
        const __half* vp = vg + kt * 64;
#pragma unroll
        for (int i = 0; i < 2; i++) {
            const int idx = i * 256 + tid;
            const int d = idx >> 3, c = idx & 7;
            cpasync16(sb + VS0 + buf * 8192 + SWZ(d * 128 + c * 16),
                      vp + (size_t)d * TZ + c * 8);
        }
    };

    const int nkt = 2 * bx + 2;     // 64-key tiles through the diagonal
    load_kv(0, 0);
    CP_COMMIT();

    uint32_t aq[4][4];              // Q fragments, loop-invariant
    float oacc[8][4];
#pragma unroll
    for (int nt = 0; nt < 8; nt++)
#pragma unroll
        for (int e = 0; e < 4; e++) oacc[nt][e] = 0.f;
    float m0 = -1e30f, m1 = -1e30f, l0 = 0.f, l1 = 0.f;

    for (int kt = 0; kt < nkt; kt++) {
        const int cur = kt & 1;
        CP_WAIT0();
        __syncthreads();            // data visible + prev buffer drained
        if (kt + 1 < nkt) { load_kv(kt + 1, cur ^ 1); CP_COMMIT(); }
        if (kt == 0) {
#pragma unroll
            for (int g = 0; g < 4; g++)
                ldsm4(aq[g], sb + QS +
                          SWZ((wid * 16 + a_r) * 128 + (g * 2 + a_c) * 16));
        }

        // warps entirely above the diagonal tile: nothing to do
        if (kt * 64 > wrow0 + 15) continue;

        // ---- S = Q K^T ----
        float sacc[8][4];
#pragma unroll
        for (int nt = 0; nt < 8; nt++)
#pragma unroll
            for (int e = 0; e < 4; e++) sacc[nt][e] = 0.f;

        const uint32_t ksb = sb + KS0 + cur * 8192;
#pragma unroll
        for (int g = 0; g < 4; g++) {
            uint32_t bf[4][4];
#pragma unroll
            for (int pt = 0; pt < 4; pt++)
                ldsm4(bf[pt], ksb + SWZ((pt * 16 + b_r) * 128 + (g * 2 + b_c) * 16));
#pragma unroll
            for (int nt = 0; nt < 8; nt++) {
                const uint32_t* bb = bf[nt >> 1];
                mma16(sacc[nt], aq[g], (nt & 1) ? bb[2] : bb[0],
                      (nt & 1) ? bb[3] : bb[1]);
            }
        }

        // ---- causal mask (only tiles straddling the diagonal) ----
        if (kt * 64 + 63 > wrow0) {
            const int r0 = wrow0 + gid, r1 = r0 + 8, k0 = kt * 64;
#pragma unroll
            for (int nt = 0; nt < 8; nt++) {
                const int key = k0 + nt * 8 + tig * 2;
                if (key     > r0) sacc[nt][0] = -1e30f;
                if (key + 1 > r0) sacc[nt][1] = -1e30f;
                if (key     > r1) sacc[nt][2] = -1e30f;
                if (key + 1 > r1) sacc[nt][3] = -1e30f;
            }
        }

        // ---- online softmax (base-2) ----
        float mx0 = -1e30f, mx1 = -1e30f;
#pragma unroll
        for (int nt = 0; nt < 8; nt++) {
            mx0 = fmaxf(mx0, fmaxf(sacc[nt][0], sacc[nt][1]));
            mx1 = fmaxf(mx1, fmaxf(sacc[nt][2], sacc[nt][3]));
        }
        mx0 = fmaxf(mx0, __shfl_xor_sync(0xffffffffu, mx0, 1));
        mx0 = fmaxf(mx0, __shfl_xor_sync(0xffffffffu, mx0, 2));
        mx1 = fmaxf(mx1, __shfl_xor_sync(0xffffffffu, mx1, 1));
        mx1 = fmaxf(mx1, __shfl_xor_sync(0xffffffffu, mx1, 2));
        const float mn0 = fmaxf(m0, mx0), mn1 = fmaxf(m1, mx1);
        const float c0 = ex2(m0 - mn0), c1 = ex2(m1 - mn1);
        m0 = mn0; m1 = mn1;
        float s0 = 0.f, s1 = 0.f;
#pragma unroll
        for (int nt = 0; nt < 8; nt++) {
            sacc[nt][0] = ex2(sacc[nt][0] - m0);
            sacc[nt][1] = ex2(sacc[nt][1] - m0);
            sacc[nt][2] = ex2(sacc[nt][2] - m1);
            sacc[nt][3] = ex2(sacc[nt][3] - m1);
            s0 += sacc[nt][0] + sacc[nt][1];
            s1 += sacc[nt][2] + sacc[nt][3];
        }
        s0 += __shfl_xor_sync(0xffffffffu, s0, 1);
        s0 += __shfl_xor_sync(0xffffffffu, s0, 2);
        s1 += __shfl_xor_sync(0xffffffffu, s1, 1);
        s1 += __shfl_xor_sync(0xffffffffu, s1, 2);
        l0 = l0 * c0 + s0;
        l1 = l1 * c1 + s1;
#pragma unroll
        for (int nt = 0; nt < 8; nt++) {
            oacc[nt][0] *= c0; oacc[nt][1] *= c0;
            oacc[nt][2] *= c1; oacc[nt][3] *= c1;
        }

        // ---- O += P V (P straight from registers: C-frag == A-frag) ----
        const uint32_t vsb = sb + VS0 + cur * 8192;
#pragma unroll
        for (int g = 0; g < 4; g++) {
            uint32_t pa[4];
            pa[0] = pack2(sacc[2 * g][0], sacc[2 * g][1]);
            pa[1] = pack2(sacc[2 * g][2], sacc[2 * g][3]);
            pa[2] = pack2(sacc[2 * g + 1][0], sacc[2 * g + 1][1]);
            pa[3] = pack2(sacc[2 * g + 1][2], sacc[2 * g + 1][3]);
            uint32_t bf[4][4];
#pragma unroll
            for (int pt = 0; pt < 4; pt++)
                ldsm4(bf[pt], vsb + SWZ((pt * 16 + b_r) * 128 + (g * 2 + b_c) * 16));
#pragma unroll
            for (int nt = 0; nt < 8; nt++) {
                const uint32_t* bb = bf[nt >> 1];
                mma16(oacc[nt], pa, (nt & 1) ? bb[2] : bb[0],
                      (nt & 1) ? bb[3] : bb[1]);
            }
        }
    }

    // ---- write O (fp16) to g_yh [B,T,C] ----
    const float i0 = 1.0f / l0, i1 = 1.0f / l1;
    __half* yp = g_yh + ((size_t)b * TZ + wrow0) * CZ + h * DD;
#pragma unroll
    for (int nt = 0; nt < 8; nt++) {
        const int d = nt * 8 + tig * 2;
        *(uint32_t*)(yp + (size_t)gid * CZ + d) =
            pack2(oacc[nt][0] * i0, oacc[nt][1] * i0);
        *(uint32_t*)(yp + (size_t)(gid + 8) * CZ + d) =
            pack2(oacc[nt][2] * i1, oacc[nt][3] * i1);
    }
}

// ---------------------------------------------------------------------------
extern "C" void kernel_launch(void* const* d_in, const int* in_sizes, int n_in,
                              void* d_out, int out_size)
{
    const float* x      = (const float*)d_in[0];
    const float* w_attn = (const float*)d_in[1];
    const float* b_attn = (const float*)d_in[2];
    const float* w_proj = (const float*)d_in[3];
    const float* b_proj = (const float*)d_in[4];
    float* out = (float*)d_out;

    void *y_ptr, *xa_ptr, *wa_ptr, *wp_ptr;
    cudaGetSymbolAddress(&y_ptr, g_yh);
    cudaGetSymbolAddress(&xa_ptr, g_xh);
    cudaGetSymbolAddress(&wa_ptr, g_wah);
    cudaGetSymbolAddress(&wp_ptr, g_wph);

    cudaFuncSetAttribute(mma_gemm<1>, cudaFuncAttributeMaxDynamicSharedMemorySize, GEMM_SMEM);
    cudaFuncSetAttribute(mma_gemm<0>, cudaFuncAttributeMaxDynamicSharedMemorySize, GEMM_SMEM);
    cudaFuncSetAttribute(attn_mma, cudaFuncAttributeMaxDynamicSharedMemorySize, ATT_SMEM);

    // 0) pre-convert inputs to fp16 (+ transpose weights to [N][K])
    cvt_x<<<M_TOT * KD / 4 / 256, 256>>>((const float4*)x, (uint2*)xa_ptr);
    wtrans<<<dim3(N_QKV / 32, KD / 32), 256>>>(w_attn, (__half*)wa_ptr, N_QKV);
    wtrans<<<dim3(CZ / 32, KD / 32), 256>>>(w_proj, (__half*)wp_ptr, CZ);

    // 1) QKV GEMM -> q(scaled)/k [B,H,T,D], v [B,H,D,T], all fp16
    mma_gemm<1><<<dim3(N_QKV / 128, M_TOT / 128), 256, GEMM_SMEM>>>(
        (const __half*)xa_ptr, (const __half*)wa_ptr, b_attn, nullptr, N_QKV);

    // 2) Flash attention (fp16 mma, 128q/block) -> g_yh [B,T,C]
    attn_mma<<<dim3(TZ / 128, HH, BZ), 256, ATT_SMEM>>>();

    // 3) Proj GEMM -> d_out (fp32)
    mma_gemm<0><<<dim3(CZ / 128, M_TOT / 128), 256, GEMM_SMEM>>>(
        (const __half*)y_ptr, (const __half*)wp_ptr, b_proj, out, CZ);
}